// round 13
// baseline (speedup 1.0000x reference)
#include <cuda_runtime.h>
#include <cstdint>

#define BB 8
#define NN 2048
#define DD 64
#define HH 64
#define CC 16
#define NROW (BB*NN)      /* 16384 */
#define NMASK (NROW*HH)   /* 1048576 */
#define KS 2              /* k-split */
#define KCH (NN/KS)       /* 1024 per CTA */

typedef unsigned long long ull;

#if defined(__CUDA_ARCH__) && (defined(__CUDA_ARCH_FEAT_SM103_ALL) || defined(__CUDA_ARCH_FEAT_SM100_ALL) || defined(__CUDA_ARCH_FEAT_SM101_ALL))
#define TC_OK 1
#else
#define TC_OK 0
#endif

// ---- scratch (static device globals; no allocation) ----
__device__ float g_dis[NROW];              // d^-1/2
__device__ float g_M1[NROW*HH];            // d_j*(X@W1), fp32 (diag term)
__device__ float g_M2[NROW*CC];            // d_j*(Hd@W2), fp32
__device__ unsigned g_M1hT[BB*HH*NN/2];    // M1^T bf16-hi pairs [b][h][n/2]
__device__ unsigned g_M1lT[BB*HH*NN/2];    // M1^T bf16-lo pairs
__device__ unsigned g_M2hT[BB*CC*NN/2];
__device__ unsigned g_M2lT[BB*CC*NN/2];
__device__ float g_p1[KS][NROW*HH];        // layer1 k-split partials (8 MB)
__device__ float g_p2[KS][NROW*CC];        // layer2 k-split partials (2 MB)

// =================== helpers ===================
__device__ __forceinline__ ull f2pack(float a, float b) {
    ull r; asm("mov.b64 %0, {%1,%2};" : "=l"(r) : "f"(a), "f"(b)); return r;
}
__device__ __forceinline__ ull f2fma(ull a, ull b, ull c) {
    ull r; asm("fma.rn.f32x2 %0, %1, %2, %3;" : "=l"(r) : "l"(a), "l"(b), "l"(c)); return r;
}
__device__ __forceinline__ float2 f2unpack(ull v) {
    float2 r; asm("mov.b64 {%0,%1}, %2;" : "=f"(r.x), "=f"(r.y) : "l"(v)); return r;
}
// split fp32 pair -> bf16x2 hi word + bf16x2 residual word; lo half = first elt
__device__ __forceinline__ void bf16split2(float a, float b, unsigned &h, unsigned &l) {
    asm("cvt.rn.bf16x2.f32 %0, %1, %2;" : "=r"(h) : "f"(b), "f"(a));
    float fa = __uint_as_float(h << 16);
    float fb = __uint_as_float(h & 0xffff0000u);
    float ra = a - fa, rb = b - fb;
    asm("cvt.rn.bf16x2.f32 %0, %1, %2;" : "=r"(l) : "f"(rb), "f"(ra));
}
// JAX partitionable threefry2x32, key=(0,42): mask multiplier for flat index i
__device__ __forceinline__ float tf_mask(unsigned i) {
    unsigned x0 = 0u, x1 = i;
    const unsigned ks0 = 0u, ks1 = 42u, ks2 = 0x1BD11BDAu ^ 0u ^ 42u;
    x0 += ks0; x1 += ks1;
#define TFR(r) { x0 += x1; x1 = (x1 << (r)) | (x1 >> (32 - (r))); x1 ^= x0; }
    TFR(13) TFR(15) TFR(26) TFR(6)
    x0 += ks1; x1 += ks2 + 1u;
    TFR(17) TFR(29) TFR(16) TFR(24)
    x0 += ks2; x1 += ks0 + 2u;
    TFR(13) TFR(15) TFR(26) TFR(6)
    x0 += ks0; x1 += ks1 + 3u;
    TFR(17) TFR(29) TFR(16) TFR(24)
    x0 += ks1; x1 += ks2 + 4u;
    TFR(13) TFR(15) TFR(26) TFR(6)
    x0 += ks2; x1 += ks0 + 5u;
#undef TFR
    return ((x0 ^ x1) >> 31) ? 0.0f : 2.0f;
}

#if TC_OK
__device__ __forceinline__ uint32_t smem_u32(const void* p) {
    uint32_t a;
    asm("{ .reg .u64 t; cvta.to.shared.u64 t, %1; cvt.u32.u64 %0, t; }" : "=r"(a) : "l"(p));
    return a;
}
__device__ __forceinline__ uint32_t elect_one() {
    uint32_t p;
    asm volatile("{\n\t.reg .pred p;\n\telect.sync _|p, 0xFFFFFFFF;\n\tselp.b32 %0, 1, 0, p;\n\t}" : "=r"(p));
    return p;
}
#define MBAR_INIT(a, n) asm volatile("mbarrier.init.shared.b64 [%0], %1;" :: "r"(a), "r"(n) : "memory")
#define MBAR_INVAL(a)   asm volatile("mbarrier.inval.shared.b64 [%0];" :: "r"(a) : "memory")
#define MBAR_WAIT(a, p) do { \
    asm volatile("{\n\t.reg .pred P1;\n\tWL%=:\n\t" \
        "mbarrier.try_wait.parity.acquire.cta.shared::cta.b64 P1, [%0], %1, 0x989680;\n\t" \
        "@P1 bra.uni WD%=;\n\tbra.uni WL%=;\n\tWD%=:\n\t}" \
        :: "r"(a), "r"(p) : "memory"); \
} while (0)
#define TC_COMMIT(a) asm volatile("tcgen05.commit.cta_group::1.mbarrier::arrive::one.shared::cluster.b64 [%0];" :: "r"(a) : "memory")
#define TC_ALLOC(sa, n)  asm volatile("tcgen05.alloc.cta_group::1.sync.aligned.shared::cta.b32 [%0], %1;" :: "r"(sa), "r"(n) : "memory")
#define TC_RELINQ()      asm volatile("tcgen05.relinquish_alloc_permit.cta_group::1.sync.aligned;")
#define TC_DEALLOC(t, n) asm volatile("tcgen05.dealloc.cta_group::1.sync.aligned.b32 %0, %1;" :: "r"(t), "r"(n))
#define TC_FENCE_AFTER() asm volatile("tcgen05.fence::after_thread_sync;" ::: "memory")
#define TC_WAIT_LD()     asm volatile("tcgen05.wait::ld.sync.aligned;" ::: "memory")
#define FENCE_ASYNC()    asm volatile("fence.proxy.async.shared::cta;" ::: "memory")

#define LDTM_X32(r, a) \
    asm volatile("tcgen05.ld.sync.aligned.32x32b.x32.b32 " \
        "{%0,%1,%2,%3,%4,%5,%6,%7,%8,%9,%10,%11,%12,%13,%14,%15," \
        "%16,%17,%18,%19,%20,%21,%22,%23,%24,%25,%26,%27,%28,%29,%30,%31}, [%32];" \
        : "=r"((r)[0]),"=r"((r)[1]),"=r"((r)[2]),"=r"((r)[3]),"=r"((r)[4]),"=r"((r)[5]),"=r"((r)[6]),"=r"((r)[7]), \
          "=r"((r)[8]),"=r"((r)[9]),"=r"((r)[10]),"=r"((r)[11]),"=r"((r)[12]),"=r"((r)[13]),"=r"((r)[14]),"=r"((r)[15]), \
          "=r"((r)[16]),"=r"((r)[17]),"=r"((r)[18]),"=r"((r)[19]),"=r"((r)[20]),"=r"((r)[21]),"=r"((r)[22]),"=r"((r)[23]), \
          "=r"((r)[24]),"=r"((r)[25]),"=r"((r)[26]),"=r"((r)[27]),"=r"((r)[28]),"=r"((r)[29]),"=r"((r)[30]),"=r"((r)[31]) \
        : "r"(a))
#define LDTM_X16(r, a) \
    asm volatile("tcgen05.ld.sync.aligned.32x32b.x16.b32 " \
        "{%0,%1,%2,%3,%4,%5,%6,%7,%8,%9,%10,%11,%12,%13,%14,%15}, [%16];" \
        : "=r"((r)[0]),"=r"((r)[1]),"=r"((r)[2]),"=r"((r)[3]),"=r"((r)[4]),"=r"((r)[5]),"=r"((r)[6]),"=r"((r)[7]), \
          "=r"((r)[8]),"=r"((r)[9]),"=r"((r)[10]),"=r"((r)[11]),"=r"((r)[12]),"=r"((r)[13]),"=r"((r)[14]),"=r"((r)[15]) \
        : "r"(a))

// SW128 K-major descriptor (layout=2, version=1, SBO=64, LBO=1)
#define DESC_BASE ((2ull << 61) | (1ull << 46) | (64ull << 32) | (1ull << 16))
#define MK_DESC(addr) (DESC_BASE | (ull)(((addr) >> 4) & 0x3FFF))

__device__ __forceinline__ void mma_bf16_ss(uint32_t d, ull ad, ull bd, uint32_t idesc, uint32_t en) {
    asm volatile("{\n\t.reg .pred p;\n\tsetp.ne.u32 p, %5, 0;\n\t"
        "tcgen05.mma.cta_group::1.kind::f16 [%0], %1, %2, %3, {%4,%4,%4,%4}, p;\n\t}"
        :: "r"(d), "l"(ad), "l"(bd), "r"(idesc), "r"(0u), "r"(en) : "memory");
}
#define IDESC1 0x8100490u   /* M=128, N=64, bf16 in, f32 acc */
#define IDESC2 0x8040490u   /* M=128, N=16 */

// streaming (evict-first) A-tile prefetch
__device__ __forceinline__ void load_A8(float4 (&av)[8], const float* Ab, int k0, int t) {
    #pragma unroll
    for (int it = 0; it < 8; it++) {
        int idx = it * 256 + t;
        int row = idx >> 4, f4 = idx & 15;
        av[it] = __ldcs(reinterpret_cast<const float4*>(Ab + (size_t)row * NN + k0 + f4 * 4));
    }
}
#endif  // TC_OK

#define SWZ(o) ((o) ^ (((o) >> 3) & 0x70))

// ============================================================
// 1) degrees
// ============================================================
__global__ void k_degree(const float* __restrict__ A) {
    int row = blockIdx.x;
    const float4* p = reinterpret_cast<const float4*>(A + (size_t)row * NN);
    int t = threadIdx.x;                        // 128
    float s = 0.f;
    #pragma unroll
    for (int i = 0; i < 4; i++) {
        float4 v = __ldcs(p + t + i * 128);
        s += (v.x + v.y) + (v.z + v.w);
    }
    #pragma unroll
    for (int o = 16; o; o >>= 1) s += __shfl_xor_sync(0xffffffffu, s, o);
    __shared__ float ws[4];
    if ((t & 31) == 0) ws[t >> 5] = s;
    __syncthreads();
    if (t == 0) g_dis[row] = rsqrtf(((ws[0] + ws[1]) + (ws[2] + ws[3])) + 1.0f);
}

// ============================================================
// 2) M1 = d_j*(X@W1): fp32 row-major + bf16 hi/lo transposed
// ============================================================
__global__ void k_xw1(const float* __restrict__ X, const float* __restrict__ W1) {
    __shared__ float Ws[DD * HH];
    __shared__ float S[32][65];
    int t = threadIdx.x;
    for (int i = t; i < DD * HH; i += 256) Ws[i] = W1[i];
    __syncthreads();
    int h = t & 63, rl = t >> 6;
    int row0 = blockIdx.x * 32;
    int b = row0 >> 11, n0 = row0 & 2047;
    for (int rr = rl; rr < 32; rr += 4) {
        int row = row0 + rr;
        const float4* x4 = reinterpret_cast<const float4*>(X + (size_t)row * DD);
        float s = 0.f;
        #pragma unroll
        for (int d4 = 0; d4 < 16; d4++) {
            float4 v = x4[d4];
            s += v.x * Ws[(d4 * 4 + 0) * HH + h];
            s += v.y * Ws[(d4 * 4 + 1) * HH + h];
            s += v.z * Ws[(d4 * 4 + 2) * HH + h];
            s += v.w * Ws[(d4 * 4 + 3) * HH + h];
        }
        float v = g_dis[row] * s;
        g_M1[(size_t)row * HH + h] = v;
        S[rr][h] = v;
    }
    __syncthreads();
    #pragma unroll
    for (int it = 0; it < 4; it++) {            // 64 h x 16 pairs
        int widx = it * 256 + t;
        int hp = widx >> 4, jp = widx & 15;
        unsigned hw, lw;
        bf16split2(S[2 * jp][hp], S[2 * jp + 1][hp], hw, lw);
        size_t w = ((size_t)(b * HH + hp) * NN + n0 + 2 * jp) >> 1;
        g_M1hT[w] = hw; g_M1lT[w] = lw;
    }
}

// ============================================================
// 3) layer1: tcgen05 bf16 3-term split GEMM, k-split x2,
//    2 CTAs/SM + A-register prefetch; writes fp32 partials
// ============================================================
#define L1_TM 0
#define L1_MB 8
#define L1_AH(s) (1024 + (s)*16384)
#define L1_AL(s) (33792 + (s)*16384)
#define L1_BH(s) (66560 + (s)*8192)
#define L1_BL(s) (82944 + (s)*8192)
#define L1_SMEM 99328

__global__ __launch_bounds__(256, 2) __cluster_dims__(1, 1, 1)
void k_layer1(const float* __restrict__ A) {
    extern __shared__ char smem[];
    const int t = threadIdx.x;
    const int b = blockIdx.y, i0 = blockIdx.x * 128, kc = blockIdx.z;
    const float* Ab = A + ((size_t)(b * NN + i0)) * NN;
#if TC_OK
    const uint32_t sb = smem_u32(smem);
    const int wid = t >> 5, lane = t & 31;

    if (wid == 0) { TC_ALLOC(sb + L1_TM, 64); TC_RELINQ(); }
    if (t == 0) { MBAR_INIT(sb + L1_MB, 1); MBAR_INIT(sb + L1_MB + 8, 1); }
    __syncthreads();
    uint32_t tb;
    asm volatile("ld.shared.b32 %0, [%1];" : "=r"(tb) : "r"(sb + L1_TM));

    // A prefetched in registers; B is L2-resident (read 16x), loaded in-loop.
    float4 av[8];
    load_A8(av, Ab, kc * KCH, t);

    #pragma unroll 2
    for (int c = 0; c < 16; c++) {
        int s = c & 1;
        if (c >= 2) MBAR_WAIT(sb + L1_MB + s * 8, ((c >> 1) - 1) & 1);
        int k0 = kc * KCH + c * 64;
        float4 avn[8];
        if (c < 15) load_A8(avn, Ab, k0 + 64, t);
        uint4 bh[2], bl[2];
        #pragma unroll
        for (int it = 0; it < 2; it++) {
            int idx = it * 256 + t;
            int hr = idx >> 3, q = idx & 7;
            size_t wo = (((size_t)(b * HH + hr) * NN + k0) >> 3) + q;
            bh[it] = reinterpret_cast<const uint4*>(g_M1hT)[wo];
            bl[it] = reinterpret_cast<const uint4*>(g_M1lT)[wo];
        }
        #pragma unroll
        for (int it = 0; it < 8; it++) {
            int idx = it * 256 + t;
            int row = idx >> 4, f4 = idx & 15;
            unsigned h0, l0, h1, l1;
            bf16split2(av[it].x, av[it].y, h0, l0);
            bf16split2(av[it].z, av[it].w, h1, l1);
            uint32_t off = SWZ(row * 128 + f4 * 8);
            asm volatile("st.shared.v2.b32 [%0], {%1,%2};" :: "r"(sb + L1_AH(s) + off), "r"(h0), "r"(h1) : "memory");
            asm volatile("st.shared.v2.b32 [%0], {%1,%2};" :: "r"(sb + L1_AL(s) + off), "r"(l0), "r"(l1) : "memory");
        }
        #pragma unroll
        for (int it = 0; it < 2; it++) {
            int idx = it * 256 + t;
            int hr = idx >> 3, q = idx & 7;
            uint32_t off = SWZ(hr * 128 + q * 16);
            asm volatile("st.shared.v4.b32 [%0], {%1,%2,%3,%4};" :: "r"(sb + L1_BH(s) + off),
                         "r"(bh[it].x), "r"(bh[it].y), "r"(bh[it].z), "r"(bh[it].w) : "memory");
            asm volatile("st.shared.v4.b32 [%0], {%1,%2,%3,%4};" :: "r"(sb + L1_BL(s) + off),
                         "r"(bl[it].x), "r"(bl[it].y), "r"(bl[it].z), "r"(bl[it].w) : "memory");
        }
        __syncthreads();
        if (wid == 0) {
            FENCE_ASYNC();
            if (elect_one()) {
                ull adh = MK_DESC(sb + L1_AH(s)), adl = MK_DESC(sb + L1_AL(s));
                ull bdh = MK_DESC(sb + L1_BH(s)), bdl = MK_DESC(sb + L1_BL(s));
                #pragma unroll
                for (int ks = 0; ks < 4; ks++) {
                    mma_bf16_ss(tb, adh + ks * 2, bdh + ks * 2, IDESC1, !(c == 0 && ks == 0));
                    mma_bf16_ss(tb, adh + ks * 2, bdl + ks * 2, IDESC1, 1);
                    mma_bf16_ss(tb, adl + ks * 2, bdh + ks * 2, IDESC1, 1);
                }
                TC_COMMIT(sb + L1_MB + s * 8);
            }
        }
        #pragma unroll
        for (int i = 0; i < 8; i++) av[i] = avn[i];
    }
    MBAR_WAIT(sb + L1_MB + 8, 1);               // 8th commit on mbar[1]
    TC_FENCE_AFTER();
    int sub = wid & 3, half = wid >> 2;
    int row_local = sub * 32 + lane;
    uint32_t dreg[32];
    LDTM_X32(dreg, tb + half * 32);
    TC_WAIT_LD();
    int gi = b * NN + i0 + row_local;
    float* P = g_p1[kc];
    size_t base4 = ((size_t)gi * HH + half * 32) >> 2;
    #pragma unroll
    for (int q = 0; q < 8; q++) {
        float4 o;
        o.x = __uint_as_float(dreg[q * 4 + 0]);
        o.y = __uint_as_float(dreg[q * 4 + 1]);
        o.z = __uint_as_float(dreg[q * 4 + 2]);
        o.w = __uint_as_float(dreg[q * 4 + 3]);
        reinterpret_cast<float4*>(P)[base4 + q] = o;
    }
    __syncthreads();
    if (t == 0) { MBAR_INVAL(sb + L1_MB); MBAR_INVAL(sb + L1_MB + 8); }
    if (wid == 0) TC_DEALLOC(tb, 64);
#else
    // ---------- FFMA2 fallback: partial over this CTA's K chunk ----------
    float (*As)[36] = reinterpret_cast<float(*)[36]>(smem);                 // 128x36
    float (*Bs)[64] = reinterpret_cast<float(*)[64]>(smem + 128 * 36 * 4);  // 32x64
    const int cg = t & 7, rg = t >> 3;
    ull acc[4][4];
    #pragma unroll
    for (int r = 0; r < 4; r++)
        #pragma unroll
        for (int c = 0; c < 4; c++) acc[r][c] = 0ull;
    for (int k0 = kc * KCH; k0 < kc * KCH + KCH; k0 += 32) {
        #pragma unroll
        for (int it = 0; it < 4; it++) {
            int idx = it * 256 + t;
            int row = idx >> 3, f4 = idx & 7;
            float4 v = *reinterpret_cast<const float4*>(Ab + (size_t)row * NN + k0 + f4 * 4);
            *reinterpret_cast<float4*>(&As[row][f4 * 4]) = v;
        }
        #pragma unroll
        for (int it = 0; it < 2; it++) {
            int idx = it * 256 + t;
            int kk = idx >> 4, f4 = idx & 15;
            float4 v = *reinterpret_cast<const float4*>(g_M1 + ((size_t)(b * NN + k0 + kk)) * HH + f4 * 4);
            *reinterpret_cast<float4*>(&Bs[kk][f4 * 4]) = v;
        }
        __syncthreads();
        #pragma unroll 8
        for (int kk = 0; kk < 32; kk++) {
            const ull* bp = reinterpret_cast<const ull*>(&Bs[kk][cg * 8]);
            ull b0 = bp[0], b1 = bp[1], b2 = bp[2], b3 = bp[3];
            #pragma unroll
            for (int r = 0; r < 4; r++) {
                float a = As[rg + 32 * r][kk];
                ull aa = f2pack(a, a);
                acc[r][0] = f2fma(aa, b0, acc[r][0]);
                acc[r][1] = f2fma(aa, b1, acc[r][1]);
                acc[r][2] = f2fma(aa, b2, acc[r][2]);
                acc[r][3] = f2fma(aa, b3, acc[r][3]);
            }
        }
        __syncthreads();
    }
    float* P = g_p1[kc];
    #pragma unroll
    for (int r = 0; r < 4; r++) {
        int gi = b * NN + i0 + rg + 32 * r;
        size_t base = (size_t)gi * HH + cg * 8;
        #pragma unroll
        for (int c = 0; c < 4; c++) {
            float2 v = f2unpack(acc[r][c]);
            *reinterpret_cast<float2*>(&P[base + c * 2]) = make_float2(v.x, v.y);
        }
    }
#endif
}

// ============================================================
// 4) k_mid: fused dropout-mask + epilogue1 + Hd@W2
//    Hd lives only in smem; writes M2 fp32 + bf16T hi/lo
//    Hd = mask * relu(d_i*(p1[0]+p1[1]+M1) + b1)
//    M2[row,c] = d_row * sum_h Hd[row,h]*W2[h,c]
// ============================================================
__global__ __launch_bounds__(256) void k_mid(const float* __restrict__ W2,
                                             const float* __restrict__ b1v) {
    __shared__ float Ws[HH * CC];     // 4KB
    __shared__ float S[64][65];       // Hd tile (16.6KB), 65 pad: conflict-free col reads
    __shared__ float S2[64][17];
    int t = threadIdx.x;
    for (int i = t; i < HH * CC; i += 256) Ws[i] = W2[i];
    int row0 = blockIdx.x * 64;
    int b = row0 >> 11, n0 = row0 & 2047;
    // phase 1: Hd tile (64 rows x 64 cols), mask computed inline
    {
        int h4 = t & 15;              // float4 col group
        int rl = t >> 4;
        for (int rr = rl; rr < 64; rr += 16) {
            int row = row0 + rr;
            size_t i4 = ((size_t)row * HH >> 2) + h4;
            float4 s = reinterpret_cast<const float4*>(g_M1)[i4];
            float4 p0 = reinterpret_cast<const float4*>(g_p1[0])[i4];
            float4 p1 = reinterpret_cast<const float4*>(g_p1[1])[i4];
            s.x += p0.x + p1.x; s.y += p0.y + p1.y;
            s.z += p0.z + p1.z; s.w += p0.w + p1.w;
            float di = g_dis[row];
            float4 bz = reinterpret_cast<const float4*>(b1v)[h4];
            unsigned mi = (unsigned)row * 64u + (unsigned)h4 * 4u;
            S[rr][h4 * 4 + 0] = fmaxf(di * s.x + bz.x, 0.f) * tf_mask(mi + 0u);
            S[rr][h4 * 4 + 1] = fmaxf(di * s.y + bz.y, 0.f) * tf_mask(mi + 1u);
            S[rr][h4 * 4 + 2] = fmaxf(di * s.z + bz.z, 0.f) * tf_mask(mi + 2u);
            S[rr][h4 * 4 + 3] = fmaxf(di * s.w + bz.w, 0.f) * tf_mask(mi + 3u);
        }
    }
    __syncthreads();
    // phase 2: M2 = d * (Hd @ W2)
    {
        int c = t & 15, rl = t >> 4;
        for (int rr = rl; rr < 64; rr += 16) {
            int row = row0 + rr;
            float sum = 0.f;
            #pragma unroll
            for (int h = 0; h < 64; h++) sum += S[rr][h] * Ws[h * CC + c];
            float v = g_dis[row] * sum;
            g_M2[(size_t)row * CC + c] = v;
            S2[rr][c] = v;
        }
    }
    __syncthreads();
    // phase 3: bf16 hi/lo transposed M2
    #pragma unroll
    for (int it = 0; it < 2; it++) {            // 16 c x 32 pairs
        int widx = it * 256 + t;
        int cp = widx >> 5, jp = widx & 31;
        unsigned hw, lw;
        bf16split2(S2[2 * jp][cp], S2[2 * jp + 1][cp], hw, lw);
        size_t w = ((size_t)(b * CC + cp) * NN + n0 + 2 * jp) >> 1;
        g_M2hT[w] = hw; g_M2lT[w] = lw;
    }
}

// ============================================================
// 5) layer2: tcgen05 bf16 split GEMM, N=16, k-split x2 + prefetch
// ============================================================
#define L2_AH(s) (1024 + (s)*16384)
#define L2_AL(s) (33792 + (s)*16384)
#define L2_BH(s) (66560 + (s)*2048)
#define L2_BL(s) (70656 + (s)*2048)
#define L2_SMEM 74752

__global__ __launch_bounds__(256, 2) __cluster_dims__(1, 1, 1)
void k_layer2(const float* __restrict__ A) {
    extern __shared__ char smem[];
    const int t = threadIdx.x;
    const int b = blockIdx.y, i0 = blockIdx.x * 128, kc = blockIdx.z;
    const float* Ab = A + ((size_t)(b * NN + i0)) * NN;
#if TC_OK
    const uint32_t sb = smem_u32(smem);
    const int wid = t >> 5, lane = t & 31;

    if (wid == 0) { TC_ALLOC(sb + L1_TM, 32); TC_RELINQ(); }
    if (t == 0) { MBAR_INIT(sb + L1_MB, 1); MBAR_INIT(sb + L1_MB + 8, 1); }
    __syncthreads();
    uint32_t tb;
    asm volatile("ld.shared.b32 %0, [%1];" : "=r"(tb) : "r"(sb + L1_TM));

    const int hr = t >> 3, q = t & 7;           // B coords (t<128)
    float4 av[8];
    load_A8(av, Ab, kc * KCH, t);

    #pragma unroll 2
    for (int c = 0; c < 16; c++) {
        int s = c & 1;
        if (c >= 2) MBAR_WAIT(sb + L1_MB + s * 8, ((c >> 1) - 1) & 1);
        int k0 = kc * KCH + c * 64;
        float4 avn[8];
        if (c < 15) load_A8(avn, Ab, k0 + 64, t);
        uint4 bh, bl;
        if (t < 128) {                           // B tiles 16x64 bf16 (L2-resident)
            size_t wo = (((size_t)(b * CC + hr) * NN + k0) >> 3) + q;
            bh = reinterpret_cast<const uint4*>(g_M2hT)[wo];
            bl = reinterpret_cast<const uint4*>(g_M2lT)[wo];
        }
        #pragma unroll
        for (int it = 0; it < 8; it++) {
            int idx = it * 256 + t;
            int row = idx >> 4, f4 = idx & 15;
            unsigned h0, l0, h1, l1;
            bf16split2(av[it].x, av[it].y, h0, l0);
            bf16split2(av[it].z, av[it].w, h1, l1);
            uint32_t off = SWZ(row * 128 + f4 * 8);
            asm volatile("st.shared.v2.b32 [%0], {%1,%2};" :: "r"(sb + L2_AH(s) + off), "r"(h0), "r"(h1) : "memory");
            asm volatile("st.shared.v2.b32 [%0], {%1,%2};" :: "r"(sb + L2_AL(s) + off), "r"(l0), "r"(l1) : "memory");
        }
        if (t < 128) {
            uint32_t off = SWZ(hr * 128 + q * 16);
            asm volatile("st.shared.v4.b32 [%0], {%1,%2,%3,%4};" :: "r"(sb + L2_BH(s) + off),
                         "r"(bh.x), "r"(bh.y), "r"(bh.z), "r"(bh.w) : "memory");
            asm volatile("st.shared.v4.b32 [%0], {%1,%2,%3,%4};" :: "r"(sb + L2_BL(s) + off),
                         "r"(bl.x), "r"(bl.y), "r"(bl.z), "r"(bl.w) : "memory");
        }
        __syncthreads();
        if (wid == 0) {
            FENCE_ASYNC();
            if (elect_one()) {
                ull adh = MK_DESC(sb + L2_AH(s)), adl = MK_DESC(sb + L2_AL(s));
                ull bdh = MK_DESC(sb + L2_BH(s)), bdl = MK_DESC(sb + L2_BL(s));
                #pragma unroll
                for (int ks = 0; ks < 4; ks++) {
                    mma_bf16_ss(tb, adh + ks * 2, bdh + ks * 2, IDESC2, !(c == 0 && ks == 0));
                    mma_bf16_ss(tb, adh + ks * 2, bdl + ks * 2, IDESC2, 1);
                    mma_bf16_ss(tb, adl + ks * 2, bdh + ks * 2, IDESC2, 1);
                }
                TC_COMMIT(sb + L1_MB + s * 8);
            }
        }
        #pragma unroll
        for (int i = 0; i < 8; i++) av[i] = avn[i];
    }
    MBAR_WAIT(sb + L1_MB + 8, 1);
    TC_FENCE_AFTER();
    if (wid < 4) {
        int row_local = wid * 32 + lane;
        uint32_t dreg[16];
        LDTM_X16(dreg, tb);
        TC_WAIT_LD();
        int gi = b * NN + i0 + row_local;
        float* P = g_p2[kc];
        size_t base4 = ((size_t)gi * CC) >> 2;
        #pragma unroll
        for (int q2 = 0; q2 < 4; q2++) {
            float4 o;
            o.x = __uint_as_float(dreg[q2 * 4 + 0]);
            o.y = __uint_as_float(dreg[q2 * 4 + 1]);
            o.z = __uint_as_float(dreg[q2 * 4 + 2]);
            o.w = __uint_as_float(dreg[q2 * 4 + 3]);
            reinterpret_cast<float4*>(P)[base4 + q2] = o;
        }
    }
    __syncthreads();
    if (t == 0) { MBAR_INVAL(sb + L1_MB); MBAR_INVAL(sb + L1_MB + 8); }
    if (wid == 0) TC_DEALLOC(tb, 32);
#else
    // ---------- FFMA2 fallback: partials ----------
    float (*As)[68] = reinterpret_cast<float(*)[68]>(smem);                 // 128x68
    float (*Bs)[16] = reinterpret_cast<float(*)[16]>(smem + 128 * 68 * 4);  // 64x16
    const int cp = t & 7, rg = t >> 3;
    ull acc[4];
    #pragma unroll
    for (int r = 0; r < 4; r++) acc[r] = 0ull;
    for (int k0 = kc * KCH; k0 < kc * KCH + KCH; k0 += 64) {
        #pragma unroll
        for (int it = 0; it < 8; it++) {
            int idx = it * 256 + t;
            int row = idx >> 4, f4 = idx & 15;
            float4 v = *reinterpret_cast<const float4*>(Ab + (size_t)row * NN + k0 + f4 * 4);
            *reinterpret_cast<float4*>(&As[row][f4 * 4]) = v;
        }
        {
            int kk = t >> 2, f4 = t & 3;
            float4 v = *reinterpret_cast<const float4*>(g_M2 + ((size_t)(b * NN + k0 + kk)) * CC + f4 * 4);
            *reinterpret_cast<float4*>(&Bs[kk][f4 * 4]) = v;
        }
        __syncthreads();
        #pragma unroll 8
        for (int kk = 0; kk < 64; kk++) {
            ull bb = *reinterpret_cast<const ull*>(&Bs[kk][cp * 2]);
            #pragma unroll
            for (int r = 0; r < 4; r++) {
                float a = As[rg + 32 * r][kk];
                acc[r] = f2fma(f2pack(a, a), bb, acc[r]);
            }
        }
        __syncthreads();
    }
    float* P = g_p2[kc];
    #pragma unroll
    for (int r = 0; r < 4; r++) {
        int gi = b * NN + i0 + rg + 32 * r;
        float2 v = f2unpack(acc[r]);
        *reinterpret_cast<float2*>(&P[(size_t)gi * CC + cp * 2]) = make_float2(v.x, v.y);
    }
#endif
}

// ============================================================
// 6) epilogue2: out = d_i*(p2[0]+p2[1] + M2[i,:]) + b2
// ============================================================
__global__ void k_ep2(const float* __restrict__ b2v, float* __restrict__ out) {
    int i4 = blockIdx.x * 256 + threadIdx.x;    // float4 index
    int row = i4 >> 2;
    int c = (i4 & 3) * 4;
    float4 s = reinterpret_cast<const float4*>(g_M2)[i4];
    #pragma unroll
    for (int kc = 0; kc < KS; kc++) {
        float4 p = reinterpret_cast<const float4*>(g_p2[kc])[i4];
        s.x += p.x; s.y += p.y; s.z += p.z; s.w += p.w;
    }
    float di = g_dis[row];
    float4 bz = *reinterpret_cast<const float4*>(b2v + c);
    float4 o;
    o.x = di * s.x + bz.x;
    o.y = di * s.y + bz.y;
    o.z = di * s.z + bz.z;
    o.w = di * s.w + bz.w;
    reinterpret_cast<float4*>(out)[i4] = o;
}

// ============================================================
extern "C" void kernel_launch(void* const* d_in, const int* in_sizes, int n_in,
                              void* d_out, int out_size) {
    const float* X  = (const float*)d_in[0];
    const float* A  = (const float*)d_in[1];
    const float* W1 = (const float*)d_in[2];
    const float* b1 = (const float*)d_in[3];
    const float* W2 = (const float*)d_in[4];
    const float* b2 = (const float*)d_in[5];
    float* out = (float*)d_out;

    cudaFuncSetAttribute(k_layer1, cudaFuncAttributeMaxDynamicSharedMemorySize, L1_SMEM);
    cudaFuncSetAttribute(k_layer2, cudaFuncAttributeMaxDynamicSharedMemorySize, L2_SMEM);

    k_degree<<<NROW, 128>>>(A);
    k_xw1<<<NROW / 32, 256>>>(X, W1);
    k_layer1<<<dim3(16, 8, KS), 256, L1_SMEM>>>(A);
    k_mid<<<NROW / 64, 256>>>(W2, b1);
    k_layer2<<<dim3(16, 8, KS), 256, L2_SMEM>>>(A);
    k_ep2<<<NROW * CC / 4 / 256, 256>>>(b2, out);
}

// round 14
// speedup vs baseline: 1.2555x; 1.2555x over previous
#include <cuda_runtime.h>
#include <cstdint>

#define BB 8
#define NN 2048
#define DD 64
#define HH 64
#define CC 16
#define NROW (BB*NN)      /* 16384 */
#define NMASK (NROW*HH)   /* 1048576 */
#define KS 2              /* k-split */
#define KCH (NN/KS)       /* 1024 per CTA */

typedef unsigned long long ull;

#if defined(__CUDA_ARCH__) && (defined(__CUDA_ARCH_FEAT_SM103_ALL) || defined(__CUDA_ARCH_FEAT_SM100_ALL) || defined(__CUDA_ARCH_FEAT_SM101_ALL))
#define TC_OK 1
#else
#define TC_OK 0
#endif

// ---- scratch (static device globals; no allocation) ----
__device__ float g_dis[NROW];              // d^-1/2
__device__ float g_M1[NROW*HH];            // d_j*(X@W1), fp32 (diag term)
__device__ float g_Hd[NROW*HH];            // layer1 out
__device__ float g_M2[NROW*CC];            // d_j*(Hd@W2), fp32
__device__ float g_mask[NMASK];            // dropout 0/2
__device__ unsigned g_M1hT[BB*HH*NN/2];    // M1^T bf16-hi pairs [b][h][n/2]
__device__ unsigned g_M1lT[BB*HH*NN/2];    // M1^T bf16-lo pairs
__device__ unsigned g_M2hT[BB*CC*NN/2];
__device__ unsigned g_M2lT[BB*CC*NN/2];
__device__ float g_p1[KS][NROW*HH];        // layer1 k-split partials (8 MB)
__device__ float g_p2[KS][NROW*CC];        // layer2 k-split partials (2 MB)

// =================== helpers ===================
__device__ __forceinline__ ull f2pack(float a, float b) {
    ull r; asm("mov.b64 %0, {%1,%2};" : "=l"(r) : "f"(a), "f"(b)); return r;
}
__device__ __forceinline__ ull f2fma(ull a, ull b, ull c) {
    ull r; asm("fma.rn.f32x2 %0, %1, %2, %3;" : "=l"(r) : "l"(a), "l"(b), "l"(c)); return r;
}
__device__ __forceinline__ float2 f2unpack(ull v) {
    float2 r; asm("mov.b64 {%0,%1}, %2;" : "=f"(r.x), "=f"(r.y) : "l"(v)); return r;
}
// split fp32 pair -> bf16x2 hi word + bf16x2 residual word; lo half = first elt
__device__ __forceinline__ void bf16split2(float a, float b, unsigned &h, unsigned &l) {
    asm("cvt.rn.bf16x2.f32 %0, %1, %2;" : "=r"(h) : "f"(b), "f"(a));
    float fa = __uint_as_float(h << 16);
    float fb = __uint_as_float(h & 0xffff0000u);
    float ra = a - fa, rb = b - fb;
    asm("cvt.rn.bf16x2.f32 %0, %1, %2;" : "=r"(l) : "f"(rb), "f"(ra));
}

#if TC_OK
__device__ __forceinline__ uint32_t smem_u32(const void* p) {
    uint32_t a;
    asm("{ .reg .u64 t; cvta.to.shared.u64 t, %1; cvt.u32.u64 %0, t; }" : "=r"(a) : "l"(p));
    return a;
}
__device__ __forceinline__ uint32_t elect_one() {
    uint32_t p;
    asm volatile("{\n\t.reg .pred p;\n\telect.sync _|p, 0xFFFFFFFF;\n\tselp.b32 %0, 1, 0, p;\n\t}" : "=r"(p));
    return p;
}
#define MBAR_INIT(a, n) asm volatile("mbarrier.init.shared.b64 [%0], %1;" :: "r"(a), "r"(n) : "memory")
#define MBAR_INVAL(a)   asm volatile("mbarrier.inval.shared.b64 [%0];" :: "r"(a) : "memory")
#define MBAR_WAIT(a, p) do { \
    asm volatile("{\n\t.reg .pred P1;\n\tWL%=:\n\t" \
        "mbarrier.try_wait.parity.acquire.cta.shared::cta.b64 P1, [%0], %1, 0x989680;\n\t" \
        "@P1 bra.uni WD%=;\n\tbra.uni WL%=;\n\tWD%=:\n\t}" \
        :: "r"(a), "r"(p) : "memory"); \
} while (0)
#define TC_COMMIT(a) asm volatile("tcgen05.commit.cta_group::1.mbarrier::arrive::one.shared::cluster.b64 [%0];" :: "r"(a) : "memory")
#define TC_ALLOC(sa, n)  asm volatile("tcgen05.alloc.cta_group::1.sync.aligned.shared::cta.b32 [%0], %1;" :: "r"(sa), "r"(n) : "memory")
#define TC_RELINQ()      asm volatile("tcgen05.relinquish_alloc_permit.cta_group::1.sync.aligned;")
#define TC_DEALLOC(t, n) asm volatile("tcgen05.dealloc.cta_group::1.sync.aligned.b32 %0, %1;" :: "r"(t), "r"(n))
#define TC_FENCE_AFTER() asm volatile("tcgen05.fence::after_thread_sync;" ::: "memory")
#define TC_WAIT_LD()     asm volatile("tcgen05.wait::ld.sync.aligned;" ::: "memory")
#define FENCE_ASYNC()    asm volatile("fence.proxy.async.shared::cta;" ::: "memory")

#define LDTM_X32(r, a) \
    asm volatile("tcgen05.ld.sync.aligned.32x32b.x32.b32 " \
        "{%0,%1,%2,%3,%4,%5,%6,%7,%8,%9,%10,%11,%12,%13,%14,%15," \
        "%16,%17,%18,%19,%20,%21,%22,%23,%24,%25,%26,%27,%28,%29,%30,%31}, [%32];" \
        : "=r"((r)[0]),"=r"((r)[1]),"=r"((r)[2]),"=r"((r)[3]),"=r"((r)[4]),"=r"((r)[5]),"=r"((r)[6]),"=r"((r)[7]), \
          "=r"((r)[8]),"=r"((r)[9]),"=r"((r)[10]),"=r"((r)[11]),"=r"((r)[12]),"=r"((r)[13]),"=r"((r)[14]),"=r"((r)[15]), \
          "=r"((r)[16]),"=r"((r)[17]),"=r"((r)[18]),"=r"((r)[19]),"=r"((r)[20]),"=r"((r)[21]),"=r"((r)[22]),"=r"((r)[23]), \
          "=r"((r)[24]),"=r"((r)[25]),"=r"((r)[26]),"=r"((r)[27]),"=r"((r)[28]),"=r"((r)[29]),"=r"((r)[30]),"=r"((r)[31]) \
        : "r"(a))
#define LDTM_X16(r, a) \
    asm volatile("tcgen05.ld.sync.aligned.32x32b.x16.b32 " \
        "{%0,%1,%2,%3,%4,%5,%6,%7,%8,%9,%10,%11,%12,%13,%14,%15}, [%16];" \
        : "=r"((r)[0]),"=r"((r)[1]),"=r"((r)[2]),"=r"((r)[3]),"=r"((r)[4]),"=r"((r)[5]),"=r"((r)[6]),"=r"((r)[7]), \
          "=r"((r)[8]),"=r"((r)[9]),"=r"((r)[10]),"=r"((r)[11]),"=r"((r)[12]),"=r"((r)[13]),"=r"((r)[14]),"=r"((r)[15]) \
        : "r"(a))

// SW128 K-major descriptor (layout=2, version=1, SBO=64, LBO=1)
#define DESC_BASE ((2ull << 61) | (1ull << 46) | (64ull << 32) | (1ull << 16))
#define MK_DESC(addr) (DESC_BASE | (ull)(((addr) >> 4) & 0x3FFF))

__device__ __forceinline__ void mma_bf16_ss(uint32_t d, ull ad, ull bd, uint32_t idesc, uint32_t en) {
    asm volatile("{\n\t.reg .pred p;\n\tsetp.ne.u32 p, %5, 0;\n\t"
        "tcgen05.mma.cta_group::1.kind::f16 [%0], %1, %2, %3, {%4,%4,%4,%4}, p;\n\t}"
        :: "r"(d), "l"(ad), "l"(bd), "r"(idesc), "r"(0u), "r"(en) : "memory");
}
#define IDESC1 0x8100490u   /* M=128, N=64, bf16 in, f32 acc */
#define IDESC2 0x8040490u   /* M=128, N=16 */

// streaming (evict-first) A-tile prefetch
__device__ __forceinline__ void load_A8(float4 (&av)[8], const float* Ab, int k0, int t) {
    #pragma unroll
    for (int it = 0; it < 8; it++) {
        int idx = it * 256 + t;
        int row = idx >> 4, f4 = idx & 15;
        av[it] = __ldcs(reinterpret_cast<const float4*>(Ab + (size_t)row * NN + k0 + f4 * 4));
    }
}
#endif  // TC_OK

#define SWZ(o) ((o) ^ (((o) >> 3) & 0x70))

// ============================================================
// 1) degrees
// ============================================================
__global__ void k_degree(const float* __restrict__ A) {
    int row = blockIdx.x;
    const float4* p = reinterpret_cast<const float4*>(A + (size_t)row * NN);
    int t = threadIdx.x;                        // 128
    float s = 0.f;
    #pragma unroll
    for (int i = 0; i < 4; i++) {
        float4 v = __ldcs(p + t + i * 128);
        s += (v.x + v.y) + (v.z + v.w);
    }
    #pragma unroll
    for (int o = 16; o; o >>= 1) s += __shfl_xor_sync(0xffffffffu, s, o);
    __shared__ float ws[4];
    if ((t & 31) == 0) ws[t >> 5] = s;
    __syncthreads();
    if (t == 0) g_dis[row] = rsqrtf(((ws[0] + ws[1]) + (ws[2] + ws[3])) + 1.0f);
}

// ============================================================
// 2) dropout mask: JAX partitionable threefry, key=(0,42)
// ============================================================
__global__ void k_mask() {
    unsigned i = blockIdx.x * 256u + threadIdx.x;
    unsigned x0 = 0u, x1 = i;
    const unsigned ks0 = 0u, ks1 = 42u, ks2 = 0x1BD11BDAu ^ 0u ^ 42u;
    x0 += ks0; x1 += ks1;
#define TFR(r) { x0 += x1; x1 = (x1 << (r)) | (x1 >> (32 - (r))); x1 ^= x0; }
    TFR(13) TFR(15) TFR(26) TFR(6)
    x0 += ks1; x1 += ks2 + 1u;
    TFR(17) TFR(29) TFR(16) TFR(24)
    x0 += ks2; x1 += ks0 + 2u;
    TFR(13) TFR(15) TFR(26) TFR(6)
    x0 += ks0; x1 += ks1 + 3u;
    TFR(17) TFR(29) TFR(16) TFR(24)
    x0 += ks1; x1 += ks2 + 4u;
    TFR(13) TFR(15) TFR(26) TFR(6)
    x0 += ks2; x1 += ks0 + 5u;
#undef TFR
    g_mask[i] = ((x0 ^ x1) >> 31) ? 0.0f : 2.0f;
}

// ============================================================
// 3) M1 = d_j*(X@W1): fp32 row-major + bf16 hi/lo transposed
// ============================================================
__global__ void k_xw1(const float* __restrict__ X, const float* __restrict__ W1) {
    __shared__ float Ws[DD * HH];
    __shared__ float S[32][65];
    int t = threadIdx.x;
    for (int i = t; i < DD * HH; i += 256) Ws[i] = W1[i];
    __syncthreads();
    int h = t & 63, rl = t >> 6;
    int row0 = blockIdx.x * 32;
    int b = row0 >> 11, n0 = row0 & 2047;
    for (int rr = rl; rr < 32; rr += 4) {
        int row = row0 + rr;
        const float4* x4 = reinterpret_cast<const float4*>(X + (size_t)row * DD);
        float s = 0.f;
        #pragma unroll
        for (int d4 = 0; d4 < 16; d4++) {
            float4 v = x4[d4];
            s += v.x * Ws[(d4 * 4 + 0) * HH + h];
            s += v.y * Ws[(d4 * 4 + 1) * HH + h];
            s += v.z * Ws[(d4 * 4 + 2) * HH + h];
            s += v.w * Ws[(d4 * 4 + 3) * HH + h];
        }
        float v = g_dis[row] * s;
        g_M1[(size_t)row * HH + h] = v;
        S[rr][h] = v;
    }
    __syncthreads();
    #pragma unroll
    for (int it = 0; it < 4; it++) {            // 64 h x 16 pairs
        int widx = it * 256 + t;
        int hp = widx >> 4, jp = widx & 15;
        unsigned hw, lw;
        bf16split2(S[2 * jp][hp], S[2 * jp + 1][hp], hw, lw);
        size_t w = ((size_t)(b * HH + hp) * NN + n0 + 2 * jp) >> 1;
        g_M1hT[w] = hw; g_M1lT[w] = lw;
    }
}

// ============================================================
// 4) layer1: tcgen05 bf16 3-term split GEMM, k-split x2,
//    2 CTAs/SM + A-register prefetch; writes fp32 partials
// ============================================================
#define L1_TM 0
#define L1_MB 8
#define L1_AH(s) (1024 + (s)*16384)
#define L1_AL(s) (33792 + (s)*16384)
#define L1_BH(s) (66560 + (s)*8192)
#define L1_BL(s) (82944 + (s)*8192)
#define L1_SMEM 99328

__global__ __launch_bounds__(256, 2) __cluster_dims__(1, 1, 1)
void k_layer1(const float* __restrict__ A) {
    extern __shared__ char smem[];
    const int t = threadIdx.x;
    const int b = blockIdx.y, i0 = blockIdx.x * 128, kc = blockIdx.z;
    const float* Ab = A + ((size_t)(b * NN + i0)) * NN;
#if TC_OK
    const uint32_t sb = smem_u32(smem);
    const int wid = t >> 5, lane = t & 31;

    if (wid == 0) { TC_ALLOC(sb + L1_TM, 64); TC_RELINQ(); }
    if (t == 0) { MBAR_INIT(sb + L1_MB, 1); MBAR_INIT(sb + L1_MB + 8, 1); }
    __syncthreads();
    uint32_t tb;
    asm volatile("ld.shared.b32 %0, [%1];" : "=r"(tb) : "r"(sb + L1_TM));

    // A prefetched in registers; B is L2-resident (read 16x), loaded in-loop.
    float4 av[8];
    load_A8(av, Ab, kc * KCH, t);

    #pragma unroll 2
    for (int c = 0; c < 16; c++) {
        int s = c & 1;
        if (c >= 2) MBAR_WAIT(sb + L1_MB + s * 8, ((c >> 1) - 1) & 1);
        int k0 = kc * KCH + c * 64;
        float4 avn[8];
        if (c < 15) load_A8(avn, Ab, k0 + 64, t);
        uint4 bh[2], bl[2];
        #pragma unroll
        for (int it = 0; it < 2; it++) {
            int idx = it * 256 + t;
            int hr = idx >> 3, q = idx & 7;
            size_t wo = (((size_t)(b * HH + hr) * NN + k0) >> 3) + q;
            bh[it] = reinterpret_cast<const uint4*>(g_M1hT)[wo];
            bl[it] = reinterpret_cast<const uint4*>(g_M1lT)[wo];
        }
        #pragma unroll
        for (int it = 0; it < 8; it++) {
            int idx = it * 256 + t;
            int row = idx >> 4, f4 = idx & 15;
            unsigned h0, l0, h1, l1;
            bf16split2(av[it].x, av[it].y, h0, l0);
            bf16split2(av[it].z, av[it].w, h1, l1);
            uint32_t off = SWZ(row * 128 + f4 * 8);
            asm volatile("st.shared.v2.b32 [%0], {%1,%2};" :: "r"(sb + L1_AH(s) + off), "r"(h0), "r"(h1) : "memory");
            asm volatile("st.shared.v2.b32 [%0], {%1,%2};" :: "r"(sb + L1_AL(s) + off), "r"(l0), "r"(l1) : "memory");
        }
        #pragma unroll
        for (int it = 0; it < 2; it++) {
            int idx = it * 256 + t;
            int hr = idx >> 3, q = idx & 7;
            uint32_t off = SWZ(hr * 128 + q * 16);
            asm volatile("st.shared.v4.b32 [%0], {%1,%2,%3,%4};" :: "r"(sb + L1_BH(s) + off),
                         "r"(bh[it].x), "r"(bh[it].y), "r"(bh[it].z), "r"(bh[it].w) : "memory");
            asm volatile("st.shared.v4.b32 [%0], {%1,%2,%3,%4};" :: "r"(sb + L1_BL(s) + off),
                         "r"(bl[it].x), "r"(bl[it].y), "r"(bl[it].z), "r"(bl[it].w) : "memory");
        }
        __syncthreads();
        if (wid == 0) {
            FENCE_ASYNC();
            if (elect_one()) {
                ull adh = MK_DESC(sb + L1_AH(s)), adl = MK_DESC(sb + L1_AL(s));
                ull bdh = MK_DESC(sb + L1_BH(s)), bdl = MK_DESC(sb + L1_BL(s));
                #pragma unroll
                for (int ks = 0; ks < 4; ks++) {
                    mma_bf16_ss(tb, adh + ks * 2, bdh + ks * 2, IDESC1, !(c == 0 && ks == 0));
                    mma_bf16_ss(tb, adh + ks * 2, bdl + ks * 2, IDESC1, 1);
                    mma_bf16_ss(tb, adl + ks * 2, bdh + ks * 2, IDESC1, 1);
                }
                TC_COMMIT(sb + L1_MB + s * 8);
            }
        }
        #pragma unroll
        for (int i = 0; i < 8; i++) av[i] = avn[i];
    }
    MBAR_WAIT(sb + L1_MB + 8, 1);               // 8th commit on mbar[1]
    TC_FENCE_AFTER();
    int sub = wid & 3, half = wid >> 2;
    int row_local = sub * 32 + lane;
    uint32_t dreg[32];
    LDTM_X32(dreg, tb + half * 32);
    TC_WAIT_LD();
    int gi = b * NN + i0 + row_local;
    float* P = g_p1[kc];
    size_t base4 = ((size_t)gi * HH + half * 32) >> 2;
    #pragma unroll
    for (int q = 0; q < 8; q++) {
        float4 o;
        o.x = __uint_as_float(dreg[q * 4 + 0]);
        o.y = __uint_as_float(dreg[q * 4 + 1]);
        o.z = __uint_as_float(dreg[q * 4 + 2]);
        o.w = __uint_as_float(dreg[q * 4 + 3]);
        reinterpret_cast<float4*>(P)[base4 + q] = o;
    }
    __syncthreads();
    if (t == 0) { MBAR_INVAL(sb + L1_MB); MBAR_INVAL(sb + L1_MB + 8); }
    if (wid == 0) TC_DEALLOC(tb, 64);
#else
    // ---------- FFMA2 fallback: partial over this CTA's K chunk ----------
    float (*As)[36] = reinterpret_cast<float(*)[36]>(smem);                 // 128x36
    float (*Bs)[64] = reinterpret_cast<float(*)[64]>(smem + 128 * 36 * 4);  // 32x64
    const int cg = t & 7, rg = t >> 3;
    ull acc[4][4];
    #pragma unroll
    for (int r = 0; r < 4; r++)
        #pragma unroll
        for (int c = 0; c < 4; c++) acc[r][c] = 0ull;
    for (int k0 = kc * KCH; k0 < kc * KCH + KCH; k0 += 32) {
        #pragma unroll
        for (int it = 0; it < 4; it++) {
            int idx = it * 256 + t;
            int row = idx >> 3, f4 = idx & 7;
            float4 v = *reinterpret_cast<const float4*>(Ab + (size_t)row * NN + k0 + f4 * 4);
            *reinterpret_cast<float4*>(&As[row][f4 * 4]) = v;
        }
        #pragma unroll
        for (int it = 0; it < 2; it++) {
            int idx = it * 256 + t;
            int kk = idx >> 4, f4 = idx & 15;
            float4 v = *reinterpret_cast<const float4*>(g_M1 + ((size_t)(b * NN + k0 + kk)) * HH + f4 * 4);
            *reinterpret_cast<float4*>(&Bs[kk][f4 * 4]) = v;
        }
        __syncthreads();
        #pragma unroll 8
        for (int kk = 0; kk < 32; kk++) {
            const ull* bp = reinterpret_cast<const ull*>(&Bs[kk][cg * 8]);
            ull b0 = bp[0], b1 = bp[1], b2 = bp[2], b3 = bp[3];
            #pragma unroll
            for (int r = 0; r < 4; r++) {
                float a = As[rg + 32 * r][kk];
                ull aa = f2pack(a, a);
                acc[r][0] = f2fma(aa, b0, acc[r][0]);
                acc[r][1] = f2fma(aa, b1, acc[r][1]);
                acc[r][2] = f2fma(aa, b2, acc[r][2]);
                acc[r][3] = f2fma(aa, b3, acc[r][3]);
            }
        }
        __syncthreads();
    }
    float* P = g_p1[kc];
    #pragma unroll
    for (int r = 0; r < 4; r++) {
        int gi = b * NN + i0 + rg + 32 * r;
        size_t base = (size_t)gi * HH + cg * 8;
        #pragma unroll
        for (int c = 0; c < 4; c++) {
            float2 v = f2unpack(acc[r][c]);
            *reinterpret_cast<float2*>(&P[base + c * 2]) = make_float2(v.x, v.y);
        }
    }
#endif
}

// ============================================================
// 4b) epilogue1: Hd = mask * relu(d_i*(p1[0]+p1[1] + M1[i,:]) + b1)
// ============================================================
__global__ void k_ep1(const float* __restrict__ b1v) {
    int i4 = blockIdx.x * 256 + threadIdx.x;    // float4 index
    int row = i4 >> 4;
    int h = (i4 & 15) * 4;
    float4 s = reinterpret_cast<const float4*>(g_M1)[i4];
    #pragma unroll
    for (int kc = 0; kc < KS; kc++) {
        float4 p = reinterpret_cast<const float4*>(g_p1[kc])[i4];
        s.x += p.x; s.y += p.y; s.z += p.z; s.w += p.w;
    }
    float di = g_dis[row];
    float4 bz = *reinterpret_cast<const float4*>(b1v + h);
    float4 mk = reinterpret_cast<const float4*>(g_mask)[i4];
    float4 o;
    o.x = fmaxf(di * s.x + bz.x, 0.f) * mk.x;
    o.y = fmaxf(di * s.y + bz.y, 0.f) * mk.y;
    o.z = fmaxf(di * s.z + bz.z, 0.f) * mk.z;
    o.w = fmaxf(di * s.w + bz.w, 0.f) * mk.w;
    reinterpret_cast<float4*>(g_Hd)[i4] = o;
}

// ============================================================
// 5) M2 = d_j*(Hd@W2): fp32 row-major + bf16 hi/lo transposed
// ============================================================
__global__ void k_hw2(const float* __restrict__ W2) {
    __shared__ float Ws[HH * CC];
    __shared__ float S2[64][17];
    int t = threadIdx.x;
    for (int i = t; i < HH * CC; i += 256) Ws[i] = W2[i];
    __syncthreads();
    int c = t & 15, rl = t >> 4;
    int row0 = blockIdx.x * 64;
    int b = row0 >> 11, n0 = row0 & 2047;
    for (int rr = rl; rr < 64; rr += 16) {
        int row = row0 + rr;
        const float4* h4 = reinterpret_cast<const float4*>(g_Hd + (size_t)row * HH);
        float s = 0.f;
        #pragma unroll
        for (int d4 = 0; d4 < 16; d4++) {
            float4 v = h4[d4];
            s += v.x * Ws[(d4 * 4 + 0) * CC + c] + v.y * Ws[(d4 * 4 + 1) * CC + c]
               + v.z * Ws[(d4 * 4 + 2) * CC + c] + v.w * Ws[(d4 * 4 + 3) * CC + c];
        }
        float v = g_dis[row] * s;
        g_M2[(size_t)row * CC + c] = v;
        S2[rr][c] = v;
    }
    __syncthreads();
    #pragma unroll
    for (int it = 0; it < 2; it++) {            // 16 c x 32 pairs
        int widx = it * 256 + t;
        int cp = widx >> 5, jp = widx & 31;
        unsigned hw, lw;
        bf16split2(S2[2 * jp][cp], S2[2 * jp + 1][cp], hw, lw);
        size_t w = ((size_t)(b * CC + cp) * NN + n0 + 2 * jp) >> 1;
        g_M2hT[w] = hw; g_M2lT[w] = lw;
    }
}

// ============================================================
// 6) layer2: tcgen05 bf16 split GEMM, N=16, k-split x2 + prefetch
// ============================================================
#define L2_AH(s) (1024 + (s)*16384)
#define L2_AL(s) (33792 + (s)*16384)
#define L2_BH(s) (66560 + (s)*2048)
#define L2_BL(s) (70656 + (s)*2048)
#define L2_SMEM 74752

__global__ __launch_bounds__(256, 2) __cluster_dims__(1, 1, 1)
void k_layer2(const float* __restrict__ A) {
    extern __shared__ char smem[];
    const int t = threadIdx.x;
    const int b = blockIdx.y, i0 = blockIdx.x * 128, kc = blockIdx.z;
    const float* Ab = A + ((size_t)(b * NN + i0)) * NN;
#if TC_OK
    const uint32_t sb = smem_u32(smem);
    const int wid = t >> 5, lane = t & 31;

    if (wid == 0) { TC_ALLOC(sb + L1_TM, 32); TC_RELINQ(); }
    if (t == 0) { MBAR_INIT(sb + L1_MB, 1); MBAR_INIT(sb + L1_MB + 8, 1); }
    __syncthreads();
    uint32_t tb;
    asm volatile("ld.shared.b32 %0, [%1];" : "=r"(tb) : "r"(sb + L1_TM));

    const int hr = t >> 3, q = t & 7;           // B coords (t<128)
    float4 av[8];
    load_A8(av, Ab, kc * KCH, t);

    #pragma unroll 2
    for (int c = 0; c < 16; c++) {
        int s = c & 1;
        if (c >= 2) MBAR_WAIT(sb + L1_MB + s * 8, ((c >> 1) - 1) & 1);
        int k0 = kc * KCH + c * 64;
        float4 avn[8];
        if (c < 15) load_A8(avn, Ab, k0 + 64, t);
        uint4 bh, bl;
        if (t < 128) {                           // B tiles 16x64 bf16 (L2-resident)
            size_t wo = (((size_t)(b * CC + hr) * NN + k0) >> 3) + q;
            bh = reinterpret_cast<const uint4*>(g_M2hT)[wo];
            bl = reinterpret_cast<const uint4*>(g_M2lT)[wo];
        }
        #pragma unroll
        for (int it = 0; it < 8; it++) {
            int idx = it * 256 + t;
            int row = idx >> 4, f4 = idx & 15;
            unsigned h0, l0, h1, l1;
            bf16split2(av[it].x, av[it].y, h0, l0);
            bf16split2(av[it].z, av[it].w, h1, l1);
            uint32_t off = SWZ(row * 128 + f4 * 8);
            asm volatile("st.shared.v2.b32 [%0], {%1,%2};" :: "r"(sb + L2_AH(s) + off), "r"(h0), "r"(h1) : "memory");
            asm volatile("st.shared.v2.b32 [%0], {%1,%2};" :: "r"(sb + L2_AL(s) + off), "r"(l0), "r"(l1) : "memory");
        }
        if (t < 128) {
            uint32_t off = SWZ(hr * 128 + q * 16);
            asm volatile("st.shared.v4.b32 [%0], {%1,%2,%3,%4};" :: "r"(sb + L2_BH(s) + off),
                         "r"(bh.x), "r"(bh.y), "r"(bh.z), "r"(bh.w) : "memory");
            asm volatile("st.shared.v4.b32 [%0], {%1,%2,%3,%4};" :: "r"(sb + L2_BL(s) + off),
                         "r"(bl.x), "r"(bl.y), "r"(bl.z), "r"(bl.w) : "memory");
        }
        __syncthreads();
        if (wid == 0) {
            FENCE_ASYNC();
            if (elect_one()) {
                ull adh = MK_DESC(sb + L2_AH(s)), adl = MK_DESC(sb + L2_AL(s));
                ull bdh = MK_DESC(sb + L2_BH(s)), bdl = MK_DESC(sb + L2_BL(s));
                #pragma unroll
                for (int ks = 0; ks < 4; ks++) {
                    mma_bf16_ss(tb, adh + ks * 2, bdh + ks * 2, IDESC2, !(c == 0 && ks == 0));
                    mma_bf16_ss(tb, adh + ks * 2, bdl + ks * 2, IDESC2, 1);
                    mma_bf16_ss(tb, adl + ks * 2, bdh + ks * 2, IDESC2, 1);
                }
                TC_COMMIT(sb + L1_MB + s * 8);
            }
        }
        #pragma unroll
        for (int i = 0; i < 8; i++) av[i] = avn[i];
    }
    MBAR_WAIT(sb + L1_MB + 8, 1);
    TC_FENCE_AFTER();
    if (wid < 4) {
        int row_local = wid * 32 + lane;
        uint32_t dreg[16];
        LDTM_X16(dreg, tb);
        TC_WAIT_LD();
        int gi = b * NN + i0 + row_local;
        float* P = g_p2[kc];
        size_t base4 = ((size_t)gi * CC) >> 2;
        #pragma unroll
        for (int q2 = 0; q2 < 4; q2++) {
            float4 o;
            o.x = __uint_as_float(dreg[q2 * 4 + 0]);
            o.y = __uint_as_float(dreg[q2 * 4 + 1]);
            o.z = __uint_as_float(dreg[q2 * 4 + 2]);
            o.w = __uint_as_float(dreg[q2 * 4 + 3]);
            reinterpret_cast<float4*>(P)[base4 + q2] = o;
        }
    }
    __syncthreads();
    if (t == 0) { MBAR_INVAL(sb + L1_MB); MBAR_INVAL(sb + L1_MB + 8); }
    if (wid == 0) TC_DEALLOC(tb, 32);
#else
    // ---------- FFMA2 fallback: partials ----------
    float (*As)[68] = reinterpret_cast<float(*)[68]>(smem);                 // 128x68
    float (*Bs)[16] = reinterpret_cast<float(*)[16]>(smem + 128 * 68 * 4);  // 64x16
    const int cp = t & 7, rg = t >> 3;
    ull acc[4];
    #pragma unroll
    for (int r = 0; r < 4; r++) acc[r] = 0ull;
    for (int k0 = kc * KCH; k0 < kc * KCH + KCH; k0 += 64) {
        #pragma unroll
        for (int it = 0; it < 8; it++) {
            int idx = it * 256 + t;
            int row = idx >> 4, f4 = idx & 15;
            float4 v = *reinterpret_cast<const float4*>(Ab + (size_t)row * NN + k0 + f4 * 4);
            *reinterpret_cast<float4*>(&As[row][f4 * 4]) = v;
        }
        {
            int kk = t >> 2, f4 = t & 3;
            float4 v = *reinterpret_cast<const float4*>(g_M2 + ((size_t)(b * NN + k0 + kk)) * CC + f4 * 4);
            *reinterpret_cast<float4*>(&Bs[kk][f4 * 4]) = v;
        }
        __syncthreads();
        #pragma unroll 8
        for (int kk = 0; kk < 64; kk++) {
            ull bb = *reinterpret_cast<const ull*>(&Bs[kk][cp * 2]);
            #pragma unroll
            for (int r = 0; r < 4; r++) {
                float a = As[rg + 32 * r][kk];
                acc[r] = f2fma(f2pack(a, a), bb, acc[r]);
            }
        }
        __syncthreads();
    }
    float* P = g_p2[kc];
    #pragma unroll
    for (int r = 0; r < 4; r++) {
        int gi = b * NN + i0 + rg + 32 * r;
        float2 v = f2unpack(acc[r]);
        *reinterpret_cast<float2*>(&P[(size_t)gi * CC + cp * 2]) = make_float2(v.x, v.y);
    }
#endif
}

// ============================================================
// 6b) epilogue2: out = d_i*(p2[0]+p2[1] + M2[i,:]) + b2
// ============================================================
__global__ void k_ep2(const float* __restrict__ b2v, float* __restrict__ out) {
    int i4 = blockIdx.x * 256 + threadIdx.x;    // float4 index
    int row = i4 >> 2;
    int c = (i4 & 3) * 4;
    float4 s = reinterpret_cast<const float4*>(g_M2)[i4];
    #pragma unroll
    for (int kc = 0; kc < KS; kc++) {
        float4 p = reinterpret_cast<const float4*>(g_p2[kc])[i4];
        s.x += p.x; s.y += p.y; s.z += p.z; s.w += p.w;
    }
    float di = g_dis[row];
    float4 bz = *reinterpret_cast<const float4*>(b2v + c);
    float4 o;
    o.x = di * s.x + bz.x;
    o.y = di * s.y + bz.y;
    o.z = di * s.z + bz.z;
    o.w = di * s.w + bz.w;
    reinterpret_cast<float4*>(out)[i4] = o;
}

// ============================================================
extern "C" void kernel_launch(void* const* d_in, const int* in_sizes, int n_in,
                              void* d_out, int out_size) {
    const float* X  = (const float*)d_in[0];
    const float* A  = (const float*)d_in[1];
    const float* W1 = (const float*)d_in[2];
    const float* b1 = (const float*)d_in[3];
    const float* W2 = (const float*)d_in[4];
    const float* b2 = (const float*)d_in[5];
    float* out = (float*)d_out;

    cudaFuncSetAttribute(k_layer1, cudaFuncAttributeMaxDynamicSharedMemorySize, L1_SMEM);
    cudaFuncSetAttribute(k_layer2, cudaFuncAttributeMaxDynamicSharedMemorySize, L2_SMEM);

    k_degree<<<NROW, 128>>>(A);
    k_mask<<<NMASK / 256, 256>>>();
    k_xw1<<<NROW / 32, 256>>>(X, W1);
    k_layer1<<<dim3(16, 8, KS), 256, L1_SMEM>>>(A);
    k_ep1<<<NMASK / 4 / 256, 256>>>(b1);
    k_hw2<<<NROW / 64, 256>>>(W2);
    k_layer2<<<dim3(16, 8, KS), 256, L2_SMEM>>>(A);
    k_ep2<<<NROW * CC / 4 / 256, 256>>>(b2, out);
}

// round 15
// speedup vs baseline: 1.2790x; 1.0187x over previous
#include <cuda_runtime.h>
#include <cstdint>

#define BB 8
#define NN 2048
#define DD 64
#define HH 64
#define CC 16
#define NROW (BB*NN)      /* 16384 */
#define NMASK (NROW*HH)   /* 1048576 */
#define KS 2              /* k-split */
#define KCH (NN/KS)       /* 1024 per CTA */

typedef unsigned long long ull;

#if defined(__CUDA_ARCH__) && (defined(__CUDA_ARCH_FEAT_SM103_ALL) || defined(__CUDA_ARCH_FEAT_SM100_ALL) || defined(__CUDA_ARCH_FEAT_SM101_ALL))
#define TC_OK 1
#else
#define TC_OK 0
#endif

// ---- scratch (static device globals; no allocation) ----
__device__ float g_dis[NROW];              // d^-1/2
__device__ float g_M1[NROW*HH];            // d_j*(X@W1), fp32 (diag term)
__device__ float g_M2[NROW*CC];            // d_j*(Hd@W2), fp32 (diag term)
__device__ float g_mask[NMASK];            // dropout 0/2
__device__ unsigned g_M1hT[BB*HH*NN/2];    // M1^T bf16-hi pairs [b][h][n/2]
__device__ unsigned g_M1lT[BB*HH*NN/2];    // M1^T bf16-lo pairs
__device__ unsigned g_M2hT[BB*CC*NN/2];
__device__ unsigned g_M2lT[BB*CC*NN/2];
__device__ float g_p1[KS][NROW*HH];        // layer1 k-split partials (8 MB)
__device__ float g_p2[KS][NROW*CC];        // layer2 k-split partials (2 MB)
__device__ unsigned g_cnt1[128];           // split-K tickets layer1 (b*16+tile)
__device__ unsigned g_cnt2[128];           // split-K tickets layer2

// =================== helpers ===================
__device__ __forceinline__ ull f2pack(float a, float b) {
    ull r; asm("mov.b64 %0, {%1,%2};" : "=l"(r) : "f"(a), "f"(b)); return r;
}
__device__ __forceinline__ ull f2fma(ull a, ull b, ull c) {
    ull r; asm("fma.rn.f32x2 %0, %1, %2, %3;" : "=l"(r) : "l"(a), "l"(b), "l"(c)); return r;
}
__device__ __forceinline__ float2 f2unpack(ull v) {
    float2 r; asm("mov.b64 {%0,%1}, %2;" : "=f"(r.x), "=f"(r.y) : "l"(v)); return r;
}
// split fp32 pair -> bf16x2 hi word + bf16x2 residual word; lo half = first elt
__device__ __forceinline__ void bf16split2(float a, float b, unsigned &h, unsigned &l) {
    asm("cvt.rn.bf16x2.f32 %0, %1, %2;" : "=r"(h) : "f"(b), "f"(a));
    float fa = __uint_as_float(h << 16);
    float fb = __uint_as_float(h & 0xffff0000u);
    float ra = a - fa, rb = b - fb;
    asm("cvt.rn.bf16x2.f32 %0, %1, %2;" : "=r"(l) : "f"(rb), "f"(ra));
}

// ============================================================
// split-K finishing epilogues (run by the 2nd-arriving CTA)
// ============================================================
// layer1 finisher: Hd (smem only) = mask*relu(d_i*(p0+p1+M1)+b1);
// then M2 = d*(Hd@W2) fp32 + bf16 hi/lo transposed.
__device__ void l1_epilogue(char* smem, int b, int i0,
                            const float* __restrict__ W2,
                            const float* __restrict__ b1v) {
    float (*S)[65]  = reinterpret_cast<float(*)[65]>(smem + 1024);
    float (*S2)[17] = reinterpret_cast<float(*)[17]>(smem + 1024 + 128 * 65 * 4);
    float* Ws       = reinterpret_cast<float*>(smem + 1024 + 128 * 65 * 4 + 128 * 17 * 4);
    const int t = threadIdx.x;
    for (int i = t; i < HH * CC; i += 256) Ws[i] = W2[i];
    // phase 1: Hd tile 128x64
    #pragma unroll
    for (int it = 0; it < 8; it++) {
        int idx = it * 256 + t;
        int r = idx >> 4, q4 = idx & 15;
        int gi = b * NN + i0 + r;
        size_t base4 = (size_t)gi * 16 + q4;
        float4 s  = reinterpret_cast<const float4*>(g_p1[0])[base4];
        float4 p  = reinterpret_cast<const float4*>(g_p1[1])[base4];
        float4 m1 = reinterpret_cast<const float4*>(g_M1)[base4];
        float4 mk = reinterpret_cast<const float4*>(g_mask)[base4];
        float4 bz = reinterpret_cast<const float4*>(b1v)[q4];
        float di = g_dis[gi];
        S[r][q4 * 4 + 0] = fmaxf(di * (s.x + p.x + m1.x) + bz.x, 0.f) * mk.x;
        S[r][q4 * 4 + 1] = fmaxf(di * (s.y + p.y + m1.y) + bz.y, 0.f) * mk.y;
        S[r][q4 * 4 + 2] = fmaxf(di * (s.z + p.z + m1.z) + bz.z, 0.f) * mk.z;
        S[r][q4 * 4 + 3] = fmaxf(di * (s.w + p.w + m1.w) + bz.w, 0.f) * mk.w;
    }
    __syncthreads();
    // phase 2: M2 = d * (Hd @ W2)
    {
        int c = t & 15, rl = t >> 4;
        #pragma unroll
        for (int k = 0; k < 8; k++) {
            int r = rl + 16 * k;
            int gi = b * NN + i0 + r;
            float sum = 0.f;
            #pragma unroll
            for (int h = 0; h < 64; h++) sum += S[r][h] * Ws[h * CC + c];
            float v = g_dis[gi] * sum;
            g_M2[(size_t)gi * CC + c] = v;
            S2[r][c] = v;
        }
    }
    __syncthreads();
    // phase 3: transposed bf16 hi/lo M2
    #pragma unroll
    for (int it = 0; it < 4; it++) {
        int widx = it * 256 + t;
        int cp = widx >> 6, jp = widx & 63;
        unsigned hw, lw;
        bf16split2(S2[2 * jp][cp], S2[2 * jp + 1][cp], hw, lw);
        size_t w = ((size_t)(b * CC + cp) * NN + i0 + 2 * jp) >> 1;
        g_M2hT[w] = hw; g_M2lT[w] = lw;
    }
}

// layer2 finisher: out = d_i*(p0+p1+M2) + b2
__device__ void l2_epilogue(int b, int i0, const float* __restrict__ b2v,
                            float* __restrict__ out) {
    const int t = threadIdx.x;
    #pragma unroll
    for (int it = 0; it < 2; it++) {
        int idx = it * 256 + t;
        int r = idx >> 2, q4 = idx & 3;
        int gi = b * NN + i0 + r;
        size_t base4 = (size_t)gi * 4 + q4;
        float4 s  = reinterpret_cast<const float4*>(g_p2[0])[base4];
        float4 p  = reinterpret_cast<const float4*>(g_p2[1])[base4];
        float4 m2 = reinterpret_cast<const float4*>(g_M2)[base4];
        float4 bz = reinterpret_cast<const float4*>(b2v)[q4];
        float di = g_dis[gi];
        float4 o;
        o.x = di * (s.x + p.x + m2.x) + bz.x;
        o.y = di * (s.y + p.y + m2.y) + bz.y;
        o.z = di * (s.z + p.z + m2.z) + bz.z;
        o.w = di * (s.w + p.w + m2.w) + bz.w;
        reinterpret_cast<float4*>(out)[base4] = o;
    }
}

#if TC_OK
__device__ __forceinline__ uint32_t smem_u32(const void* p) {
    uint32_t a;
    asm("{ .reg .u64 t; cvta.to.shared.u64 t, %1; cvt.u32.u64 %0, t; }" : "=r"(a) : "l"(p));
    return a;
}
__device__ __forceinline__ uint32_t elect_one() {
    uint32_t p;
    asm volatile("{\n\t.reg .pred p;\n\telect.sync _|p, 0xFFFFFFFF;\n\tselp.b32 %0, 1, 0, p;\n\t}" : "=r"(p));
    return p;
}
#define MBAR_INIT(a, n) asm volatile("mbarrier.init.shared.b64 [%0], %1;" :: "r"(a), "r"(n) : "memory")
#define MBAR_INVAL(a)   asm volatile("mbarrier.inval.shared.b64 [%0];" :: "r"(a) : "memory")
#define MBAR_WAIT(a, p) do { \
    asm volatile("{\n\t.reg .pred P1;\n\tWL%=:\n\t" \
        "mbarrier.try_wait.parity.acquire.cta.shared::cta.b64 P1, [%0], %1, 0x989680;\n\t" \
        "@P1 bra.uni WD%=;\n\tbra.uni WL%=;\n\tWD%=:\n\t}" \
        :: "r"(a), "r"(p) : "memory"); \
} while (0)
#define TC_COMMIT(a) asm volatile("tcgen05.commit.cta_group::1.mbarrier::arrive::one.shared::cluster.b64 [%0];" :: "r"(a) : "memory")
#define TC_ALLOC(sa, n)  asm volatile("tcgen05.alloc.cta_group::1.sync.aligned.shared::cta.b32 [%0], %1;" :: "r"(sa), "r"(n) : "memory")
#define TC_RELINQ()      asm volatile("tcgen05.relinquish_alloc_permit.cta_group::1.sync.aligned;")
#define TC_DEALLOC(t, n) asm volatile("tcgen05.dealloc.cta_group::1.sync.aligned.b32 %0, %1;" :: "r"(t), "r"(n))
#define TC_FENCE_AFTER() asm volatile("tcgen05.fence::after_thread_sync;" ::: "memory")
#define TC_WAIT_LD()     asm volatile("tcgen05.wait::ld.sync.aligned;" ::: "memory")
#define FENCE_ASYNC()    asm volatile("fence.proxy.async.shared::cta;" ::: "memory")

#define LDTM_X32(r, a) \
    asm volatile("tcgen05.ld.sync.aligned.32x32b.x32.b32 " \
        "{%0,%1,%2,%3,%4,%5,%6,%7,%8,%9,%10,%11,%12,%13,%14,%15," \
        "%16,%17,%18,%19,%20,%21,%22,%23,%24,%25,%26,%27,%28,%29,%30,%31}, [%32];" \
        : "=r"((r)[0]),"=r"((r)[1]),"=r"((r)[2]),"=r"((r)[3]),"=r"((r)[4]),"=r"((r)[5]),"=r"((r)[6]),"=r"((r)[7]), \
          "=r"((r)[8]),"=r"((r)[9]),"=r"((r)[10]),"=r"((r)[11]),"=r"((r)[12]),"=r"((r)[13]),"=r"((r)[14]),"=r"((r)[15]), \
          "=r"((r)[16]),"=r"((r)[17]),"=r"((r)[18]),"=r"((r)[19]),"=r"((r)[20]),"=r"((r)[21]),"=r"((r)[22]),"=r"((r)[23]), \
          "=r"((r)[24]),"=r"((r)[25]),"=r"((r)[26]),"=r"((r)[27]),"=r"((r)[28]),"=r"((r)[29]),"=r"((r)[30]),"=r"((r)[31]) \
        : "r"(a))
#define LDTM_X16(r, a) \
    asm volatile("tcgen05.ld.sync.aligned.32x32b.x16.b32 " \
        "{%0,%1,%2,%3,%4,%5,%6,%7,%8,%9,%10,%11,%12,%13,%14,%15}, [%16];" \
        : "=r"((r)[0]),"=r"((r)[1]),"=r"((r)[2]),"=r"((r)[3]),"=r"((r)[4]),"=r"((r)[5]),"=r"((r)[6]),"=r"((r)[7]), \
          "=r"((r)[8]),"=r"((r)[9]),"=r"((r)[10]),"=r"((r)[11]),"=r"((r)[12]),"=r"((r)[13]),"=r"((r)[14]),"=r"((r)[15]) \
        : "r"(a))

// SW128 K-major descriptor (layout=2, version=1, SBO=64, LBO=1)
#define DESC_BASE ((2ull << 61) | (1ull << 46) | (64ull << 32) | (1ull << 16))
#define MK_DESC(addr) (DESC_BASE | (ull)(((addr) >> 4) & 0x3FFF))

__device__ __forceinline__ void mma_bf16_ss(uint32_t d, ull ad, ull bd, uint32_t idesc, uint32_t en) {
    asm volatile("{\n\t.reg .pred p;\n\tsetp.ne.u32 p, %5, 0;\n\t"
        "tcgen05.mma.cta_group::1.kind::f16 [%0], %1, %2, %3, {%4,%4,%4,%4}, p;\n\t}"
        :: "r"(d), "l"(ad), "l"(bd), "r"(idesc), "r"(0u), "r"(en) : "memory");
}
#define IDESC1 0x8100490u   /* M=128, N=64, bf16 in, f32 acc */
#define IDESC2 0x8040490u   /* M=128, N=16 */

// streaming (evict-first) A-tile prefetch
__device__ __forceinline__ void load_A8(float4 (&av)[8], const float* Ab, int k0, int t) {
    #pragma unroll
    for (int it = 0; it < 8; it++) {
        int idx = it * 256 + t;
        int row = idx >> 4, f4 = idx & 15;
        av[it] = __ldcs(reinterpret_cast<const float4*>(Ab + (size_t)row * NN + k0 + f4 * 4));
    }
}
#endif  // TC_OK

#define SWZ(o) ((o) ^ (((o) >> 3) & 0x70))

// ============================================================
// 1) degrees (+ ticket counter reset for this launch)
// ============================================================
__global__ void k_degree(const float* __restrict__ A) {
    int row = blockIdx.x;
    if (blockIdx.x < 128 && threadIdx.x == 0) { g_cnt1[blockIdx.x] = 0u; g_cnt2[blockIdx.x] = 0u; }
    const float4* p = reinterpret_cast<const float4*>(A + (size_t)row * NN);
    int t = threadIdx.x;                        // 128
    float s = 0.f;
    #pragma unroll
    for (int i = 0; i < 4; i++) {
        float4 v = __ldcs(p + t + i * 128);
        s += (v.x + v.y) + (v.z + v.w);
    }
    #pragma unroll
    for (int o = 16; o; o >>= 1) s += __shfl_xor_sync(0xffffffffu, s, o);
    __shared__ float ws[4];
    if ((t & 31) == 0) ws[t >> 5] = s;
    __syncthreads();
    if (t == 0) g_dis[row] = rsqrtf(((ws[0] + ws[1]) + (ws[2] + ws[3])) + 1.0f);
}

// ============================================================
// 2) dropout mask: JAX partitionable threefry, key=(0,42)
// ============================================================
__global__ void k_mask() {
    unsigned i = blockIdx.x * 256u + threadIdx.x;
    unsigned x0 = 0u, x1 = i;
    const unsigned ks0 = 0u, ks1 = 42u, ks2 = 0x1BD11BDAu ^ 0u ^ 42u;
    x0 += ks0; x1 += ks1;
#define TFR(r) { x0 += x1; x1 = (x1 << (r)) | (x1 >> (32 - (r))); x1 ^= x0; }
    TFR(13) TFR(15) TFR(26) TFR(6)
    x0 += ks1; x1 += ks2 + 1u;
    TFR(17) TFR(29) TFR(16) TFR(24)
    x0 += ks2; x1 += ks0 + 2u;
    TFR(13) TFR(15) TFR(26) TFR(6)
    x0 += ks0; x1 += ks1 + 3u;
    TFR(17) TFR(29) TFR(16) TFR(24)
    x0 += ks1; x1 += ks2 + 4u;
    TFR(13) TFR(15) TFR(26) TFR(6)
    x0 += ks2; x1 += ks0 + 5u;
#undef TFR
    g_mask[i] = ((x0 ^ x1) >> 31) ? 0.0f : 2.0f;
}

// ============================================================
// 3) M1 = d_j*(X@W1): fp32 row-major + bf16 hi/lo transposed
// ============================================================
__global__ void k_xw1(const float* __restrict__ X, const float* __restrict__ W1) {
    __shared__ float Ws[DD * HH];
    __shared__ float S[32][65];
    int t = threadIdx.x;
    for (int i = t; i < DD * HH; i += 256) Ws[i] = W1[i];
    __syncthreads();
    int h = t & 63, rl = t >> 6;
    int row0 = blockIdx.x * 32;
    int b = row0 >> 11, n0 = row0 & 2047;
    for (int rr = rl; rr < 32; rr += 4) {
        int row = row0 + rr;
        const float4* x4 = reinterpret_cast<const float4*>(X + (size_t)row * DD);
        float s = 0.f;
        #pragma unroll
        for (int d4 = 0; d4 < 16; d4++) {
            float4 v = x4[d4];
            s += v.x * Ws[(d4 * 4 + 0) * HH + h];
            s += v.y * Ws[(d4 * 4 + 1) * HH + h];
            s += v.z * Ws[(d4 * 4 + 2) * HH + h];
            s += v.w * Ws[(d4 * 4 + 3) * HH + h];
        }
        float v = g_dis[row] * s;
        g_M1[(size_t)row * HH + h] = v;
        S[rr][h] = v;
    }
    __syncthreads();
    #pragma unroll
    for (int it = 0; it < 4; it++) {            // 64 h x 16 pairs
        int widx = it * 256 + t;
        int hp = widx >> 4, jp = widx & 15;
        unsigned hw, lw;
        bf16split2(S[2 * jp][hp], S[2 * jp + 1][hp], hw, lw);
        size_t w = ((size_t)(b * HH + hp) * NN + n0 + 2 * jp) >> 1;
        g_M1hT[w] = hw; g_M1lT[w] = lw;
    }
}

// ============================================================
// 4) layer1: tcgen05 bf16 3-term split GEMM, k-split x2,
//    2 CTAs/SM + A-register prefetch; split-K ticket finisher
//    runs fused ep1+hw2 (Hd stays in smem).
// ============================================================
#define L1_TM 0
#define L1_MB 8
#define L1_AH(s) (1024 + (s)*16384)
#define L1_AL(s) (33792 + (s)*16384)
#define L1_BH(s) (66560 + (s)*8192)
#define L1_BL(s) (82944 + (s)*8192)
#define L1_SMEM 99328

__global__ __launch_bounds__(256, 2) __cluster_dims__(1, 1, 1)
void k_layer1(const float* __restrict__ A, const float* __restrict__ W2,
              const float* __restrict__ b1v) {
    extern __shared__ char smem[];
    const int t = threadIdx.x;
    const int b = blockIdx.y, i0 = blockIdx.x * 128, kc = blockIdx.z;
    const float* Ab = A + ((size_t)(b * NN + i0)) * NN;
    int* sflag = reinterpret_cast<int*>(smem + 512);
#if TC_OK
    const uint32_t sb = smem_u32(smem);
    const int wid = t >> 5, lane = t & 31;

    if (wid == 0) { TC_ALLOC(sb + L1_TM, 64); TC_RELINQ(); }
    if (t == 0) { MBAR_INIT(sb + L1_MB, 1); MBAR_INIT(sb + L1_MB + 8, 1); }
    __syncthreads();
    uint32_t tb;
    asm volatile("ld.shared.b32 %0, [%1];" : "=r"(tb) : "r"(sb + L1_TM));

    float4 av[8];
    load_A8(av, Ab, kc * KCH, t);

    #pragma unroll 2
    for (int c = 0; c < 16; c++) {
        int s = c & 1;
        if (c >= 2) MBAR_WAIT(sb + L1_MB + s * 8, ((c >> 1) - 1) & 1);
        int k0 = kc * KCH + c * 64;
        float4 avn[8];
        if (c < 15) load_A8(avn, Ab, k0 + 64, t);
        uint4 bh[2], bl[2];
        #pragma unroll
        for (int it = 0; it < 2; it++) {
            int idx = it * 256 + t;
            int hr = idx >> 3, q = idx & 7;
            size_t wo = (((size_t)(b * HH + hr) * NN + k0) >> 3) + q;
            bh[it] = reinterpret_cast<const uint4*>(g_M1hT)[wo];
            bl[it] = reinterpret_cast<const uint4*>(g_M1lT)[wo];
        }
        #pragma unroll
        for (int it = 0; it < 8; it++) {
            int idx = it * 256 + t;
            int row = idx >> 4, f4 = idx & 15;
            unsigned h0, l0, h1, l1;
            bf16split2(av[it].x, av[it].y, h0, l0);
            bf16split2(av[it].z, av[it].w, h1, l1);
            uint32_t off = SWZ(row * 128 + f4 * 8);
            asm volatile("st.shared.v2.b32 [%0], {%1,%2};" :: "r"(sb + L1_AH(s) + off), "r"(h0), "r"(h1) : "memory");
            asm volatile("st.shared.v2.b32 [%0], {%1,%2};" :: "r"(sb + L1_AL(s) + off), "r"(l0), "r"(l1) : "memory");
        }
        #pragma unroll
        for (int it = 0; it < 2; it++) {
            int idx = it * 256 + t;
            int hr = idx >> 3, q = idx & 7;
            uint32_t off = SWZ(hr * 128 + q * 16);
            asm volatile("st.shared.v4.b32 [%0], {%1,%2,%3,%4};" :: "r"(sb + L1_BH(s) + off),
                         "r"(bh[it].x), "r"(bh[it].y), "r"(bh[it].z), "r"(bh[it].w) : "memory");
            asm volatile("st.shared.v4.b32 [%0], {%1,%2,%3,%4};" :: "r"(sb + L1_BL(s) + off),
                         "r"(bl[it].x), "r"(bl[it].y), "r"(bl[it].z), "r"(bl[it].w) : "memory");
        }
        __syncthreads();
        if (wid == 0) {
            FENCE_ASYNC();
            if (elect_one()) {
                ull adh = MK_DESC(sb + L1_AH(s)), adl = MK_DESC(sb + L1_AL(s));
                ull bdh = MK_DESC(sb + L1_BH(s)), bdl = MK_DESC(sb + L1_BL(s));
                #pragma unroll
                for (int ks = 0; ks < 4; ks++) {
                    mma_bf16_ss(tb, adh + ks * 2, bdh + ks * 2, IDESC1, !(c == 0 && ks == 0));
                    mma_bf16_ss(tb, adh + ks * 2, bdl + ks * 2, IDESC1, 1);
                    mma_bf16_ss(tb, adl + ks * 2, bdh + ks * 2, IDESC1, 1);
                }
                TC_COMMIT(sb + L1_MB + s * 8);
            }
        }
        #pragma unroll
        for (int i = 0; i < 8; i++) av[i] = avn[i];
    }
    MBAR_WAIT(sb + L1_MB + 8, 1);               // 8th commit on mbar[1]
    TC_FENCE_AFTER();
    {
        int sub = wid & 3, half = wid >> 2;
        int row_local = sub * 32 + lane;
        uint32_t dreg[32];
        LDTM_X32(dreg, tb + half * 32);
        TC_WAIT_LD();
        int gi = b * NN + i0 + row_local;
        float* P = g_p1[kc];
        size_t base4 = ((size_t)gi * HH + half * 32) >> 2;
        #pragma unroll
        for (int q = 0; q < 8; q++) {
            float4 o;
            o.x = __uint_as_float(dreg[q * 4 + 0]);
            o.y = __uint_as_float(dreg[q * 4 + 1]);
            o.z = __uint_as_float(dreg[q * 4 + 2]);
            o.w = __uint_as_float(dreg[q * 4 + 3]);
            reinterpret_cast<float4*>(P)[base4 + q] = o;
        }
    }
    __threadfence();
    __syncthreads();
    if (t == 0) { MBAR_INVAL(sb + L1_MB); MBAR_INVAL(sb + L1_MB + 8); }
    if (wid == 0) TC_DEALLOC(tb, 64);
    if (t == 0) { *sflag = (int)atomicAdd(&g_cnt1[b * 16 + blockIdx.x], 1u); __threadfence(); }
    __syncthreads();
    if (*sflag == 0) return;                    // first CTA: partial published, done
    l1_epilogue(smem, b, i0, W2, b1v);          // second CTA: finish tile
#else
    // ---------- FFMA2 fallback: partial over this CTA's K chunk ----------
    float (*As)[36] = reinterpret_cast<float(*)[36]>(smem + 1024);
    float (*Bs)[64] = reinterpret_cast<float(*)[64]>(smem + 1024 + 128 * 36 * 4);
    const int cg = t & 7, rg = t >> 3;
    ull acc[4][4];
    #pragma unroll
    for (int r = 0; r < 4; r++)
        #pragma unroll
        for (int c = 0; c < 4; c++) acc[r][c] = 0ull;
    for (int k0 = kc * KCH; k0 < kc * KCH + KCH; k0 += 32) {
        #pragma unroll
        for (int it = 0; it < 4; it++) {
            int idx = it * 256 + t;
            int row = idx >> 3, f4 = idx & 7;
            float4 v = *reinterpret_cast<const float4*>(Ab + (size_t)row * NN + k0 + f4 * 4);
            *reinterpret_cast<float4*>(&As[row][f4 * 4]) = v;
        }
        #pragma unroll
        for (int it = 0; it < 2; it++) {
            int idx = it * 256 + t;
            int kk = idx >> 4, f4 = idx & 15;
            float4 v = *reinterpret_cast<const float4*>(g_M1 + ((size_t)(b * NN + k0 + kk)) * HH + f4 * 4);
            *reinterpret_cast<float4*>(&Bs[kk][f4 * 4]) = v;
        }
        __syncthreads();
        #pragma unroll 8
        for (int kk = 0; kk < 32; kk++) {
            const ull* bp = reinterpret_cast<const ull*>(&Bs[kk][cg * 8]);
            ull b0 = bp[0], b1 = bp[1], b2 = bp[2], b3 = bp[3];
            #pragma unroll
            for (int r = 0; r < 4; r++) {
                float a = As[rg + 32 * r][kk];
                ull aa = f2pack(a, a);
                acc[r][0] = f2fma(aa, b0, acc[r][0]);
                acc[r][1] = f2fma(aa, b1, acc[r][1]);
                acc[r][2] = f2fma(aa, b2, acc[r][2]);
                acc[r][3] = f2fma(aa, b3, acc[r][3]);
            }
        }
        __syncthreads();
    }
    float* P = g_p1[kc];
    #pragma unroll
    for (int r = 0; r < 4; r++) {
        int gi = b * NN + i0 + rg + 32 * r;
        size_t base = (size_t)gi * HH + cg * 8;
        #pragma unroll
        for (int c = 0; c < 4; c++) {
            float2 v = f2unpack(acc[r][c]);
            *reinterpret_cast<float2*>(&P[base + c * 2]) = make_float2(v.x, v.y);
        }
    }
    __threadfence();
    __syncthreads();
    if (t == 0) { *sflag = (int)atomicAdd(&g_cnt1[b * 16 + blockIdx.x], 1u); __threadfence(); }
    __syncthreads();
    if (*sflag == 0) return;
    l1_epilogue(smem, b, i0, W2, b1v);
#endif
}

// ============================================================
// 5) layer2: tcgen05 bf16 split GEMM, N=16, k-split x2 + prefetch;
//    split-K ticket finisher writes final output.
// ============================================================
#define L2_AH(s) (1024 + (s)*16384)
#define L2_AL(s) (33792 + (s)*16384)
#define L2_BH(s) (66560 + (s)*2048)
#define L2_BL(s) (70656 + (s)*2048)
#define L2_SMEM 74752

__global__ __launch_bounds__(256, 2) __cluster_dims__(1, 1, 1)
void k_layer2(const float* __restrict__ A, const float* __restrict__ b2v,
              float* __restrict__ out) {
    extern __shared__ char smem[];
    const int t = threadIdx.x;
    const int b = blockIdx.y, i0 = blockIdx.x * 128, kc = blockIdx.z;
    const float* Ab = A + ((size_t)(b * NN + i0)) * NN;
    int* sflag = reinterpret_cast<int*>(smem + 512);
#if TC_OK
    const uint32_t sb = smem_u32(smem);
    const int wid = t >> 5, lane = t & 31;

    if (wid == 0) { TC_ALLOC(sb + L1_TM, 32); TC_RELINQ(); }
    if (t == 0) { MBAR_INIT(sb + L1_MB, 1); MBAR_INIT(sb + L1_MB + 8, 1); }
    __syncthreads();
    uint32_t tb;
    asm volatile("ld.shared.b32 %0, [%1];" : "=r"(tb) : "r"(sb + L1_TM));

    const int hr = t >> 3, q = t & 7;           // B coords (t<128)
    float4 av[8];
    load_A8(av, Ab, kc * KCH, t);

    #pragma unroll 2
    for (int c = 0; c < 16; c++) {
        int s = c & 1;
        if (c >= 2) MBAR_WAIT(sb + L1_MB + s * 8, ((c >> 1) - 1) & 1);
        int k0 = kc * KCH + c * 64;
        float4 avn[8];
        if (c < 15) load_A8(avn, Ab, k0 + 64, t);
        uint4 bh, bl;
        if (t < 128) {                           // B tiles 16x64 bf16 (L2-resident)
            size_t wo = (((size_t)(b * CC + hr) * NN + k0) >> 3) + q;
            bh = reinterpret_cast<const uint4*>(g_M2hT)[wo];
            bl = reinterpret_cast<const uint4*>(g_M2lT)[wo];
        }
        #pragma unroll
        for (int it = 0; it < 8; it++) {
            int idx = it * 256 + t;
            int row = idx >> 4, f4 = idx & 15;
            unsigned h0, l0, h1, l1;
            bf16split2(av[it].x, av[it].y, h0, l0);
            bf16split2(av[it].z, av[it].w, h1, l1);
            uint32_t off = SWZ(row * 128 + f4 * 8);
            asm volatile("st.shared.v2.b32 [%0], {%1,%2};" :: "r"(sb + L2_AH(s) + off), "r"(h0), "r"(h1) : "memory");
            asm volatile("st.shared.v2.b32 [%0], {%1,%2};" :: "r"(sb + L2_AL(s) + off), "r"(l0), "r"(l1) : "memory");
        }
        if (t < 128) {
            uint32_t off = SWZ(hr * 128 + q * 16);
            asm volatile("st.shared.v4.b32 [%0], {%1,%2,%3,%4};" :: "r"(sb + L2_BH(s) + off),
                         "r"(bh.x), "r"(bh.y), "r"(bh.z), "r"(bh.w) : "memory");
            asm volatile("st.shared.v4.b32 [%0], {%1,%2,%3,%4};" :: "r"(sb + L2_BL(s) + off),
                         "r"(bl.x), "r"(bl.y), "r"(bl.z), "r"(bl.w) : "memory");
        }
        __syncthreads();
        if (wid == 0) {
            FENCE_ASYNC();
            if (elect_one()) {
                ull adh = MK_DESC(sb + L2_AH(s)), adl = MK_DESC(sb + L2_AL(s));
                ull bdh = MK_DESC(sb + L2_BH(s)), bdl = MK_DESC(sb + L2_BL(s));
                #pragma unroll
                for (int ks = 0; ks < 4; ks++) {
                    mma_bf16_ss(tb, adh + ks * 2, bdh + ks * 2, IDESC2, !(c == 0 && ks == 0));
                    mma_bf16_ss(tb, adh + ks * 2, bdl + ks * 2, IDESC2, 1);
                    mma_bf16_ss(tb, adl + ks * 2, bdh + ks * 2, IDESC2, 1);
                }
                TC_COMMIT(sb + L1_MB + s * 8);
            }
        }
        #pragma unroll
        for (int i = 0; i < 8; i++) av[i] = avn[i];
    }
    MBAR_WAIT(sb + L1_MB + 8, 1);
    TC_FENCE_AFTER();
    if (wid < 4) {
        int row_local = wid * 32 + lane;
        uint32_t dreg[16];
        LDTM_X16(dreg, tb);
        TC_WAIT_LD();
        int gi = b * NN + i0 + row_local;
        float* P = g_p2[kc];
        size_t base4 = ((size_t)gi * CC) >> 2;
        #pragma unroll
        for (int q2 = 0; q2 < 4; q2++) {
            float4 o;
            o.x = __uint_as_float(dreg[q2 * 4 + 0]);
            o.y = __uint_as_float(dreg[q2 * 4 + 1]);
            o.z = __uint_as_float(dreg[q2 * 4 + 2]);
            o.w = __uint_as_float(dreg[q2 * 4 + 3]);
            reinterpret_cast<float4*>(P)[base4 + q2] = o;
        }
    }
    __threadfence();
    __syncthreads();
    if (t == 0) { MBAR_INVAL(sb + L1_MB); MBAR_INVAL(sb + L1_MB + 8); }
    if (wid == 0) TC_DEALLOC(tb, 32);
    if (t == 0) { *sflag = (int)atomicAdd(&g_cnt2[b * 16 + blockIdx.x], 1u); __threadfence(); }
    __syncthreads();
    if (*sflag == 0) return;
    l2_epilogue(b, i0, b2v, out);
#else
    // ---------- FFMA2 fallback: partials ----------
    float (*As)[68] = reinterpret_cast<float(*)[68]>(smem + 1024);
    float (*Bs)[16] = reinterpret_cast<float(*)[16]>(smem + 1024 + 128 * 68 * 4);
    const int cp = t & 7, rg = t >> 3;
    ull acc[4];
    #pragma unroll
    for (int r = 0; r < 4; r++) acc[r] = 0ull;
    for (int k0 = kc * KCH; k0 < kc * KCH + KCH; k0 += 64) {
        #pragma unroll
        for (int it = 0; it < 8; it++) {
            int idx = it * 256 + t;
            int row = idx >> 4, f4 = idx & 15;
            float4 v = *reinterpret_cast<const float4*>(Ab + (size_t)row * NN + k0 + f4 * 4);
            *reinterpret_cast<float4*>(&As[row][f4 * 4]) = v;
        }
        {
            int kk = t >> 2, f4 = t & 3;
            float4 v = *reinterpret_cast<const float4*>(g_M2 + ((size_t)(b * NN + k0 + kk)) * CC + f4 * 4);
            *reinterpret_cast<float4*>(&Bs[kk][f4 * 4]) = v;
        }
        __syncthreads();
        #pragma unroll 8
        for (int kk = 0; kk < 64; kk++) {
            ull bb = *reinterpret_cast<const ull*>(&Bs[kk][cp * 2]);
            #pragma unroll
            for (int r = 0; r < 4; r++) {
                float a = As[rg + 32 * r][kk];
                acc[r] = f2fma(f2pack(a, a), bb, acc[r]);
            }
        }
        __syncthreads();
    }
    float* P = g_p2[kc];
    #pragma unroll
    for (int r = 0; r < 4; r++) {
        int gi = b * NN + i0 + rg + 32 * r;
        float2 v = f2unpack(acc[r]);
        *reinterpret_cast<float2*>(&P[(size_t)gi * CC + cp * 2]) = make_float2(v.x, v.y);
    }
    __threadfence();
    __syncthreads();
    if (t == 0) { *sflag = (int)atomicAdd(&g_cnt2[b * 16 + blockIdx.x], 1u); __threadfence(); }
    __syncthreads();
    if (*sflag == 0) return;
    l2_epilogue(b, i0, b2v, out);
#endif
}

// ============================================================
extern "C" void kernel_launch(void* const* d_in, const int* in_sizes, int n_in,
                              void* d_out, int out_size) {
    const float* X  = (const float*)d_in[0];
    const float* A  = (const float*)d_in[1];
    const float* W1 = (const float*)d_in[2];
    const float* b1 = (const float*)d_in[3];
    const float* W2 = (const float*)d_in[4];
    const float* b2 = (const float*)d_in[5];
    float* out = (float*)d_out;

    cudaFuncSetAttribute(k_layer1, cudaFuncAttributeMaxDynamicSharedMemorySize, L1_SMEM);
    cudaFuncSetAttribute(k_layer2, cudaFuncAttributeMaxDynamicSharedMemorySize, L2_SMEM);

    k_degree<<<NROW, 128>>>(A);
    k_mask<<<NMASK / 256, 256>>>();
    k_xw1<<<NROW / 32, 256>>>(X, W1);
    k_layer1<<<dim3(16, 8, KS), 256, L1_SMEM>>>(A, W2, b1);
    k_layer2<<<dim3(16, 8, KS), 256, L2_SMEM>>>(A, b2, out);
}

// round 16
// speedup vs baseline: 1.3038x; 1.0194x over previous
#include <cuda_runtime.h>
#include <cstdint>

#define BB 8
#define NN 2048
#define DD 64
#define HH 64
#define CC 16
#define NROW (BB*NN)      /* 16384 */
#define NMASK (NROW*HH)   /* 1048576 */
#define KS 2              /* k-split */
#define KCH (NN/KS)       /* 1024 per CTA */

typedef unsigned long long ull;

#if defined(__CUDA_ARCH__) && (defined(__CUDA_ARCH_FEAT_SM103_ALL) || defined(__CUDA_ARCH_FEAT_SM100_ALL) || defined(__CUDA_ARCH_FEAT_SM101_ALL))
#define TC_OK 1
#else
#define TC_OK 0
#endif

// ---- scratch (static device globals; no allocation) ----
__device__ float g_dis[NROW];              // d^-1/2
__device__ float g_M1[NROW*HH];            // d_j*(X@W1), fp32 (diag term)
__device__ float g_M2[NROW*CC];            // d_j*(Hd@W2), fp32 (diag term)
__device__ float g_mask[NMASK];            // dropout 0/2
__device__ unsigned g_M1hT[BB*HH*NN/2];    // M1^T bf16-hi pairs [b][h][n/2]
__device__ unsigned g_M1lT[BB*HH*NN/2];    // M1^T bf16-lo pairs
__device__ unsigned g_M2hT[BB*CC*NN/2];
__device__ unsigned g_M2lT[BB*CC*NN/2];
__device__ float g_p1[KS][NROW*HH];        // layer1 k-split partials (8 MB)
__device__ float g_p2[KS][NROW*CC];        // layer2 k-split partials (2 MB)
__device__ unsigned g_cnt1[128];           // split-K tickets layer1 (b*16+tile)
__device__ unsigned g_cnt2[128];           // split-K tickets layer2

// =================== helpers ===================
__device__ __forceinline__ ull f2pack(float a, float b) {
    ull r; asm("mov.b64 %0, {%1,%2};" : "=l"(r) : "f"(a), "f"(b)); return r;
}
__device__ __forceinline__ ull f2fma(ull a, ull b, ull c) {
    ull r; asm("fma.rn.f32x2 %0, %1, %2, %3;" : "=l"(r) : "l"(a), "l"(b), "l"(c)); return r;
}
__device__ __forceinline__ float2 f2unpack(ull v) {
    float2 r; asm("mov.b64 {%0,%1}, %2;" : "=f"(r.x), "=f"(r.y) : "l"(v)); return r;
}
// split fp32 pair -> bf16x2 hi word + bf16x2 residual word; lo half = first elt
__device__ __forceinline__ void bf16split2(float a, float b, unsigned &h, unsigned &l) {
    asm("cvt.rn.bf16x2.f32 %0, %1, %2;" : "=r"(h) : "f"(b), "f"(a));
    float fa = __uint_as_float(h << 16);
    float fb = __uint_as_float(h & 0xffff0000u);
    float ra = a - fa, rb = b - fb;
    asm("cvt.rn.bf16x2.f32 %0, %1, %2;" : "=r"(l) : "f"(rb), "f"(ra));
}
// JAX partitionable threefry2x32, key=(0,42): mask multiplier for flat index i
__device__ __forceinline__ float tf_mask(unsigned i) {
    unsigned x0 = 0u, x1 = i;
    const unsigned ks0 = 0u, ks1 = 42u, ks2 = 0x1BD11BDAu ^ 0u ^ 42u;
    x0 += ks0; x1 += ks1;
#define TFR(r) { x0 += x1; x1 = (x1 << (r)) | (x1 >> (32 - (r))); x1 ^= x0; }
    TFR(13) TFR(15) TFR(26) TFR(6)
    x0 += ks1; x1 += ks2 + 1u;
    TFR(17) TFR(29) TFR(16) TFR(24)
    x0 += ks2; x1 += ks0 + 2u;
    TFR(13) TFR(15) TFR(26) TFR(6)
    x0 += ks0; x1 += ks1 + 3u;
    TFR(17) TFR(29) TFR(16) TFR(24)
    x0 += ks1; x1 += ks2 + 4u;
    TFR(13) TFR(15) TFR(26) TFR(6)
    x0 += ks2; x1 += ks0 + 5u;
#undef TFR
    return ((x0 ^ x1) >> 31) ? 0.0f : 2.0f;
}

// ============================================================
// split-K finishing epilogues (run by the 2nd-arriving CTA)
// ============================================================
__device__ void l1_epilogue(char* smem, int b, int i0,
                            const float* __restrict__ W2,
                            const float* __restrict__ b1v) {
    float (*S)[65]  = reinterpret_cast<float(*)[65]>(smem + 1024);
    float (*S2)[17] = reinterpret_cast<float(*)[17]>(smem + 1024 + 128 * 65 * 4);
    float* Ws       = reinterpret_cast<float*>(smem + 1024 + 128 * 65 * 4 + 128 * 17 * 4);
    const int t = threadIdx.x;
    for (int i = t; i < HH * CC; i += 256) Ws[i] = W2[i];
    // phase 1: Hd tile 128x64
    #pragma unroll
    for (int it = 0; it < 8; it++) {
        int idx = it * 256 + t;
        int r = idx >> 4, q4 = idx & 15;
        int gi = b * NN + i0 + r;
        size_t base4 = (size_t)gi * 16 + q4;
        float4 s  = reinterpret_cast<const float4*>(g_p1[0])[base4];
        float4 p  = reinterpret_cast<const float4*>(g_p1[1])[base4];
        float4 m1 = reinterpret_cast<const float4*>(g_M1)[base4];
        float4 mk = reinterpret_cast<const float4*>(g_mask)[base4];
        float4 bz = reinterpret_cast<const float4*>(b1v)[q4];
        float di = g_dis[gi];
        S[r][q4 * 4 + 0] = fmaxf(di * (s.x + p.x + m1.x) + bz.x, 0.f) * mk.x;
        S[r][q4 * 4 + 1] = fmaxf(di * (s.y + p.y + m1.y) + bz.y, 0.f) * mk.y;
        S[r][q4 * 4 + 2] = fmaxf(di * (s.z + p.z + m1.z) + bz.z, 0.f) * mk.z;
        S[r][q4 * 4 + 3] = fmaxf(di * (s.w + p.w + m1.w) + bz.w, 0.f) * mk.w;
    }
    __syncthreads();
    // phase 2: M2 = d * (Hd @ W2)
    {
        int c = t & 15, rl = t >> 4;
        #pragma unroll
        for (int k = 0; k < 8; k++) {
            int r = rl + 16 * k;
            int gi = b * NN + i0 + r;
            float sum = 0.f;
            #pragma unroll
            for (int h = 0; h < 64; h++) sum += S[r][h] * Ws[h * CC + c];
            float v = g_dis[gi] * sum;
            g_M2[(size_t)gi * CC + c] = v;
            S2[r][c] = v;
        }
    }
    __syncthreads();
    // phase 3: transposed bf16 hi/lo M2
    #pragma unroll
    for (int it = 0; it < 4; it++) {
        int widx = it * 256 + t;
        int cp = widx >> 6, jp = widx & 63;
        unsigned hw, lw;
        bf16split2(S2[2 * jp][cp], S2[2 * jp + 1][cp], hw, lw);
        size_t w = ((size_t)(b * CC + cp) * NN + i0 + 2 * jp) >> 1;
        g_M2hT[w] = hw; g_M2lT[w] = lw;
    }
}

// layer2 finisher: out = d_i*(p0+p1+M2) + b2
__device__ void l2_epilogue(int b, int i0, const float* __restrict__ b2v,
                            float* __restrict__ out) {
    const int t = threadIdx.x;
    #pragma unroll
    for (int it = 0; it < 2; it++) {
        int idx = it * 256 + t;
        int r = idx >> 2, q4 = idx & 3;
        int gi = b * NN + i0 + r;
        size_t base4 = (size_t)gi * 4 + q4;
        float4 s  = reinterpret_cast<const float4*>(g_p2[0])[base4];
        float4 p  = reinterpret_cast<const float4*>(g_p2[1])[base4];
        float4 m2 = reinterpret_cast<const float4*>(g_M2)[base4];
        float4 bz = reinterpret_cast<const float4*>(b2v)[q4];
        float di = g_dis[gi];
        float4 o;
        o.x = di * (s.x + p.x + m2.x) + bz.x;
        o.y = di * (s.y + p.y + m2.y) + bz.y;
        o.z = di * (s.z + p.z + m2.z) + bz.z;
        o.w = di * (s.w + p.w + m2.w) + bz.w;
        reinterpret_cast<float4*>(out)[base4] = o;
    }
}

#if TC_OK
__device__ __forceinline__ uint32_t smem_u32(const void* p) {
    uint32_t a;
    asm("{ .reg .u64 t; cvta.to.shared.u64 t, %1; cvt.u32.u64 %0, t; }" : "=r"(a) : "l"(p));
    return a;
}
__device__ __forceinline__ uint32_t elect_one() {
    uint32_t p;
    asm volatile("{\n\t.reg .pred p;\n\telect.sync _|p, 0xFFFFFFFF;\n\tselp.b32 %0, 1, 0, p;\n\t}" : "=r"(p));
    return p;
}
#define MBAR_INIT(a, n) asm volatile("mbarrier.init.shared.b64 [%0], %1;" :: "r"(a), "r"(n) : "memory")
#define MBAR_INVAL(a)   asm volatile("mbarrier.inval.shared.b64 [%0];" :: "r"(a) : "memory")
#define MBAR_WAIT(a, p) do { \
    asm volatile("{\n\t.reg .pred P1;\n\tWL%=:\n\t" \
        "mbarrier.try_wait.parity.acquire.cta.shared::cta.b64 P1, [%0], %1, 0x989680;\n\t" \
        "@P1 bra.uni WD%=;\n\tbra.uni WL%=;\n\tWD%=:\n\t}" \
        :: "r"(a), "r"(p) : "memory"); \
} while (0)
#define TC_COMMIT(a) asm volatile("tcgen05.commit.cta_group::1.mbarrier::arrive::one.shared::cluster.b64 [%0];" :: "r"(a) : "memory")
#define TC_ALLOC(sa, n)  asm volatile("tcgen05.alloc.cta_group::1.sync.aligned.shared::cta.b32 [%0], %1;" :: "r"(sa), "r"(n) : "memory")
#define TC_RELINQ()      asm volatile("tcgen05.relinquish_alloc_permit.cta_group::1.sync.aligned;")
#define TC_DEALLOC(t, n) asm volatile("tcgen05.dealloc.cta_group::1.sync.aligned.b32 %0, %1;" :: "r"(t), "r"(n))
#define TC_FENCE_AFTER() asm volatile("tcgen05.fence::after_thread_sync;" ::: "memory")
#define TC_WAIT_LD()     asm volatile("tcgen05.wait::ld.sync.aligned;" ::: "memory")
#define FENCE_ASYNC()    asm volatile("fence.proxy.async.shared::cta;" ::: "memory")

#define LDTM_X32(r, a) \
    asm volatile("tcgen05.ld.sync.aligned.32x32b.x32.b32 " \
        "{%0,%1,%2,%3,%4,%5,%6,%7,%8,%9,%10,%11,%12,%13,%14,%15," \
        "%16,%17,%18,%19,%20,%21,%22,%23,%24,%25,%26,%27,%28,%29,%30,%31}, [%32];" \
        : "=r"((r)[0]),"=r"((r)[1]),"=r"((r)[2]),"=r"((r)[3]),"=r"((r)[4]),"=r"((r)[5]),"=r"((r)[6]),"=r"((r)[7]), \
          "=r"((r)[8]),"=r"((r)[9]),"=r"((r)[10]),"=r"((r)[11]),"=r"((r)[12]),"=r"((r)[13]),"=r"((r)[14]),"=r"((r)[15]), \
          "=r"((r)[16]),"=r"((r)[17]),"=r"((r)[18]),"=r"((r)[19]),"=r"((r)[20]),"=r"((r)[21]),"=r"((r)[22]),"=r"((r)[23]), \
          "=r"((r)[24]),"=r"((r)[25]),"=r"((r)[26]),"=r"((r)[27]),"=r"((r)[28]),"=r"((r)[29]),"=r"((r)[30]),"=r"((r)[31]) \
        : "r"(a))
#define LDTM_X16(r, a) \
    asm volatile("tcgen05.ld.sync.aligned.32x32b.x16.b32 " \
        "{%0,%1,%2,%3,%4,%5,%6,%7,%8,%9,%10,%11,%12,%13,%14,%15}, [%16];" \
        : "=r"((r)[0]),"=r"((r)[1]),"=r"((r)[2]),"=r"((r)[3]),"=r"((r)[4]),"=r"((r)[5]),"=r"((r)[6]),"=r"((r)[7]), \
          "=r"((r)[8]),"=r"((r)[9]),"=r"((r)[10]),"=r"((r)[11]),"=r"((r)[12]),"=r"((r)[13]),"=r"((r)[14]),"=r"((r)[15]) \
        : "r"(a))

// SW128 K-major descriptor (layout=2, version=1, SBO=64, LBO=1)
#define DESC_BASE ((2ull << 61) | (1ull << 46) | (64ull << 32) | (1ull << 16))
#define MK_DESC(addr) (DESC_BASE | (ull)(((addr) >> 4) & 0x3FFF))

__device__ __forceinline__ void mma_bf16_ss(uint32_t d, ull ad, ull bd, uint32_t idesc, uint32_t en) {
    asm volatile("{\n\t.reg .pred p;\n\tsetp.ne.u32 p, %5, 0;\n\t"
        "tcgen05.mma.cta_group::1.kind::f16 [%0], %1, %2, %3, {%4,%4,%4,%4}, p;\n\t}"
        :: "r"(d), "l"(ad), "l"(bd), "r"(idesc), "r"(0u), "r"(en) : "memory");
}
#define IDESC1 0x8100490u   /* M=128, N=64, bf16 in, f32 acc */
#define IDESC2 0x8040490u   /* M=128, N=16 */

// streaming (evict-first) A-tile prefetch
__device__ __forceinline__ void load_A8(float4 (&av)[8], const float* Ab, int k0, int t) {
    #pragma unroll
    for (int it = 0; it < 8; it++) {
        int idx = it * 256 + t;
        int row = idx >> 4, f4 = idx & 15;
        av[it] = __ldcs(reinterpret_cast<const float4*>(Ab + (size_t)row * NN + k0 + f4 * 4));
    }
}
#endif  // TC_OK

#define SWZ(o) ((o) ^ (((o) >> 3) & 0x70))

// ============================================================
// 1) k_pre: fused degrees + dropout mask + M1=d*(X@W1) (+transposed
//    bf16 split) + ticket reset. CTA = 8 rows; the 64KB/CTA A rowsum
//    stream saturates DRAM while mask/xw1 ALU rides underneath.
// ============================================================
__global__ __launch_bounds__(256) void k_pre(const float* __restrict__ A,
                                             const float* __restrict__ X,
                                             const float* __restrict__ W1) {
    __shared__ float Ws[DD * HH];     // 16KB
    __shared__ float Xs[8 * DD];      // 2KB
    __shared__ float S[8][65];
    __shared__ float ds[8];
    const int t = threadIdx.x;
    const int w = t >> 5, lane = t & 31;
    const int row0 = blockIdx.x * 8;
    const int b = row0 >> 11, n0 = row0 & 2047;
    if (blockIdx.x < 128 && t == 0) { g_cnt1[blockIdx.x] = 0u; g_cnt2[blockIdx.x] = 0u; }

    // stage W1 + X rows
    for (int i = t; i < DD * HH; i += 256) Ws[i] = W1[i];
    reinterpret_cast<float2*>(Xs)[t] =
        reinterpret_cast<const float2*>(X + (size_t)row0 * DD)[t];

    // degree: warp w sums row row0+w (2048 floats = 64/lane)
    {
        const float4* p = reinterpret_cast<const float4*>(A + (size_t)(row0 + w) * NN);
        float s = 0.f;
        #pragma unroll
        for (int i = 0; i < 16; i++) {
            float4 v = __ldcs(p + lane + i * 32);
            s += (v.x + v.y) + (v.z + v.w);
        }
        #pragma unroll
        for (int o = 16; o; o >>= 1) s += __shfl_xor_sync(0xffffffffu, s, o);
        if (lane == 0) {
            float d = rsqrtf(s + 1.0f);
            ds[w] = d;
            g_dis[row0 + w] = d;
        }
    }
    // dropout mask for these 8 rows (512 values)
    {
        unsigned mi0 = (unsigned)row0 * 64u;
        g_mask[mi0 + t] = tf_mask(mi0 + t);
        g_mask[mi0 + 256u + t] = tf_mask(mi0 + 256u + t);
    }
    __syncthreads();
    // M1 rows: thread (h = t&63, r = t>>6 and r+4)
    {
        int h = t & 63, r2 = t >> 6;
        #pragma unroll
        for (int k = 0; k < 2; k++) {
            int r = r2 + 4 * k;
            float sum = 0.f;
            #pragma unroll
            for (int d = 0; d < DD; d++) sum += Xs[r * DD + d] * Ws[d * HH + h];
            float v = ds[r] * sum;
            g_M1[(size_t)(row0 + r) * HH + h] = v;
            S[r][h] = v;
        }
    }
    __syncthreads();
    // transposed bf16 hi/lo pairs (rows 2p,2p+1 adjacent -> same word)
    {
        int h = t & 63, pp = t >> 6;   // 4 pairs
        unsigned hw, lw;
        bf16split2(S[2 * pp][h], S[2 * pp + 1][h], hw, lw);
        size_t widx = ((size_t)(b * HH + h) * NN + n0 + 2 * pp) >> 1;
        g_M1hT[widx] = hw; g_M1lT[widx] = lw;
    }
}

// ============================================================
// 2) layer1: tcgen05 bf16 3-term split GEMM, k-split x2,
//    2 CTAs/SM + A-register prefetch; split-K ticket finisher
// ============================================================
#define L1_TM 0
#define L1_MB 8
#define L1_AH(s) (1024 + (s)*16384)
#define L1_AL(s) (33792 + (s)*16384)
#define L1_BH(s) (66560 + (s)*8192)
#define L1_BL(s) (82944 + (s)*8192)
#define L1_SMEM 99328

__global__ __launch_bounds__(256, 2) __cluster_dims__(1, 1, 1)
void k_layer1(const float* __restrict__ A, const float* __restrict__ W2,
              const float* __restrict__ b1v) {
    extern __shared__ char smem[];
    const int t = threadIdx.x;
    const int b = blockIdx.y, i0 = blockIdx.x * 128, kc = blockIdx.z;
    const float* Ab = A + ((size_t)(b * NN + i0)) * NN;
    int* sflag = reinterpret_cast<int*>(smem + 512);
#if TC_OK
    const uint32_t sb = smem_u32(smem);
    const int wid = t >> 5, lane = t & 31;

    if (wid == 0) { TC_ALLOC(sb + L1_TM, 64); TC_RELINQ(); }
    if (t == 0) { MBAR_INIT(sb + L1_MB, 1); MBAR_INIT(sb + L1_MB + 8, 1); }
    __syncthreads();
    uint32_t tb;
    asm volatile("ld.shared.b32 %0, [%1];" : "=r"(tb) : "r"(sb + L1_TM));

    float4 av[8];
    load_A8(av, Ab, kc * KCH, t);

    #pragma unroll 2
    for (int c = 0; c < 16; c++) {
        int s = c & 1;
        if (c >= 2) MBAR_WAIT(sb + L1_MB + s * 8, ((c >> 1) - 1) & 1);
        int k0 = kc * KCH + c * 64;
        float4 avn[8];
        if (c < 15) load_A8(avn, Ab, k0 + 64, t);
        uint4 bh[2], bl[2];
        #pragma unroll
        for (int it = 0; it < 2; it++) {
            int idx = it * 256 + t;
            int hr = idx >> 3, q = idx & 7;
            size_t wo = (((size_t)(b * HH + hr) * NN + k0) >> 3) + q;
            bh[it] = reinterpret_cast<const uint4*>(g_M1hT)[wo];
            bl[it] = reinterpret_cast<const uint4*>(g_M1lT)[wo];
        }
        #pragma unroll
        for (int it = 0; it < 8; it++) {
            int idx = it * 256 + t;
            int row = idx >> 4, f4 = idx & 15;
            unsigned h0, l0, h1, l1;
            bf16split2(av[it].x, av[it].y, h0, l0);
            bf16split2(av[it].z, av[it].w, h1, l1);
            uint32_t off = SWZ(row * 128 + f4 * 8);
            asm volatile("st.shared.v2.b32 [%0], {%1,%2};" :: "r"(sb + L1_AH(s) + off), "r"(h0), "r"(h1) : "memory");
            asm volatile("st.shared.v2.b32 [%0], {%1,%2};" :: "r"(sb + L1_AL(s) + off), "r"(l0), "r"(l1) : "memory");
        }
        #pragma unroll
        for (int it = 0; it < 2; it++) {
            int idx = it * 256 + t;
            int hr = idx >> 3, q = idx & 7;
            uint32_t off = SWZ(hr * 128 + q * 16);
            asm volatile("st.shared.v4.b32 [%0], {%1,%2,%3,%4};" :: "r"(sb + L1_BH(s) + off),
                         "r"(bh[it].x), "r"(bh[it].y), "r"(bh[it].z), "r"(bh[it].w) : "memory");
            asm volatile("st.shared.v4.b32 [%0], {%1,%2,%3,%4};" :: "r"(sb + L1_BL(s) + off),
                         "r"(bl[it].x), "r"(bl[it].y), "r"(bl[it].z), "r"(bl[it].w) : "memory");
        }
        __syncthreads();
        if (wid == 0) {
            FENCE_ASYNC();
            if (elect_one()) {
                ull adh = MK_DESC(sb + L1_AH(s)), adl = MK_DESC(sb + L1_AL(s));
                ull bdh = MK_DESC(sb + L1_BH(s)), bdl = MK_DESC(sb + L1_BL(s));
                #pragma unroll
                for (int ks = 0; ks < 4; ks++) {
                    mma_bf16_ss(tb, adh + ks * 2, bdh + ks * 2, IDESC1, !(c == 0 && ks == 0));
                    mma_bf16_ss(tb, adh + ks * 2, bdl + ks * 2, IDESC1, 1);
                    mma_bf16_ss(tb, adl + ks * 2, bdh + ks * 2, IDESC1, 1);
                }
                TC_COMMIT(sb + L1_MB + s * 8);
            }
        }
        #pragma unroll
        for (int i = 0; i < 8; i++) av[i] = avn[i];
    }
    MBAR_WAIT(sb + L1_MB + 8, 1);               // 8th commit on mbar[1]
    TC_FENCE_AFTER();
    {
        int sub = wid & 3, half = wid >> 2;
        int row_local = sub * 32 + lane;
        uint32_t dreg[32];
        LDTM_X32(dreg, tb + half * 32);
        TC_WAIT_LD();
        int gi = b * NN + i0 + row_local;
        float* P = g_p1[kc];
        size_t base4 = ((size_t)gi * HH + half * 32) >> 2;
        #pragma unroll
        for (int q = 0; q < 8; q++) {
            float4 o;
            o.x = __uint_as_float(dreg[q * 4 + 0]);
            o.y = __uint_as_float(dreg[q * 4 + 1]);
            o.z = __uint_as_float(dreg[q * 4 + 2]);
            o.w = __uint_as_float(dreg[q * 4 + 3]);
            reinterpret_cast<float4*>(P)[base4 + q] = o;
        }
    }
    __threadfence();
    __syncthreads();
    if (t == 0) { MBAR_INVAL(sb + L1_MB); MBAR_INVAL(sb + L1_MB + 8); }
    if (wid == 0) TC_DEALLOC(tb, 64);
    if (t == 0) { *sflag = (int)atomicAdd(&g_cnt1[b * 16 + blockIdx.x], 1u); __threadfence(); }
    __syncthreads();
    if (*sflag == 0) return;                    // first CTA: partial published, done
    l1_epilogue(smem, b, i0, W2, b1v);          // second CTA: finish tile
#else
    // ---------- FFMA2 fallback: partial over this CTA's K chunk ----------
    float (*As)[36] = reinterpret_cast<float(*)[36]>(smem + 1024);
    float (*Bs)[64] = reinterpret_cast<float(*)[64]>(smem + 1024 + 128 * 36 * 4);
    const int cg = t & 7, rg = t >> 3;
    ull acc[4][4];
    #pragma unroll
    for (int r = 0; r < 4; r++)
        #pragma unroll
        for (int c = 0; c < 4; c++) acc[r][c] = 0ull;
    for (int k0 = kc * KCH; k0 < kc * KCH + KCH; k0 += 32) {
        #pragma unroll
        for (int it = 0; it < 4; it++) {
            int idx = it * 256 + t;
            int row = idx >> 3, f4 = idx & 7;
            float4 v = *reinterpret_cast<const float4*>(Ab + (size_t)row * NN + k0 + f4 * 4);
            *reinterpret_cast<float4*>(&As[row][f4 * 4]) = v;
        }
        #pragma unroll
        for (int it = 0; it < 2; it++) {
            int idx = it * 256 + t;
            int kk = idx >> 4, f4 = idx & 15;
            float4 v = *reinterpret_cast<const float4*>(g_M1 + ((size_t)(b * NN + k0 + kk)) * HH + f4 * 4);
            *reinterpret_cast<float4*>(&Bs[kk][f4 * 4]) = v;
        }
        __syncthreads();
        #pragma unroll 8
        for (int kk = 0; kk < 32; kk++) {
            const ull* bp = reinterpret_cast<const ull*>(&Bs[kk][cg * 8]);
            ull b0 = bp[0], b1 = bp[1], b2 = bp[2], b3 = bp[3];
            #pragma unroll
            for (int r = 0; r < 4; r++) {
                float a = As[rg + 32 * r][kk];
                ull aa = f2pack(a, a);
                acc[r][0] = f2fma(aa, b0, acc[r][0]);
                acc[r][1] = f2fma(aa, b1, acc[r][1]);
                acc[r][2] = f2fma(aa, b2, acc[r][2]);
                acc[r][3] = f2fma(aa, b3, acc[r][3]);
            }
        }
        __syncthreads();
    }
    float* P = g_p1[kc];
    #pragma unroll
    for (int r = 0; r < 4; r++) {
        int gi = b * NN + i0 + rg + 32 * r;
        size_t base = (size_t)gi * HH + cg * 8;
        #pragma unroll
        for (int c = 0; c < 4; c++) {
            float2 v = f2unpack(acc[r][c]);
            *reinterpret_cast<float2*>(&P[base + c * 2]) = make_float2(v.x, v.y);
        }
    }
    __threadfence();
    __syncthreads();
    if (t == 0) { *sflag = (int)atomicAdd(&g_cnt1[b * 16 + blockIdx.x], 1u); __threadfence(); }
    __syncthreads();
    if (*sflag == 0) return;
    l1_epilogue(smem, b, i0, W2, b1v);
#endif
}

// ============================================================
// 3) layer2: tcgen05 bf16 split GEMM, N=16, k-split x2 + prefetch;
//    split-K ticket finisher writes final output.
// ============================================================
#define L2_AH(s) (1024 + (s)*16384)
#define L2_AL(s) (33792 + (s)*16384)
#define L2_BH(s) (66560 + (s)*2048)
#define L2_BL(s) (70656 + (s)*2048)
#define L2_SMEM 74752

__global__ __launch_bounds__(256, 2) __cluster_dims__(1, 1, 1)
void k_layer2(const float* __restrict__ A, const float* __restrict__ b2v,
              float* __restrict__ out) {
    extern __shared__ char smem[];
    const int t = threadIdx.x;
    const int b = blockIdx.y, i0 = blockIdx.x * 128, kc = blockIdx.z;
    const float* Ab = A + ((size_t)(b * NN + i0)) * NN;
    int* sflag = reinterpret_cast<int*>(smem + 512);
#if TC_OK
    const uint32_t sb = smem_u32(smem);
    const int wid = t >> 5, lane = t & 31;

    if (wid == 0) { TC_ALLOC(sb + L1_TM, 32); TC_RELINQ(); }
    if (t == 0) { MBAR_INIT(sb + L1_MB, 1); MBAR_INIT(sb + L1_MB + 8, 1); }
    __syncthreads();
    uint32_t tb;
    asm volatile("ld.shared.b32 %0, [%1];" : "=r"(tb) : "r"(sb + L1_TM));

    const int hr = t >> 3, q = t & 7;           // B coords (t<128)
    float4 av[8];
    load_A8(av, Ab, kc * KCH, t);

    #pragma unroll 2
    for (int c = 0; c < 16; c++) {
        int s = c & 1;
        if (c >= 2) MBAR_WAIT(sb + L1_MB + s * 8, ((c >> 1) - 1) & 1);
        int k0 = kc * KCH + c * 64;
        float4 avn[8];
        if (c < 15) load_A8(avn, Ab, k0 + 64, t);
        uint4 bh, bl;
        if (t < 128) {                           // B tiles 16x64 bf16 (L2-resident)
            size_t wo = (((size_t)(b * CC + hr) * NN + k0) >> 3) + q;
            bh = reinterpret_cast<const uint4*>(g_M2hT)[wo];
            bl = reinterpret_cast<const uint4*>(g_M2lT)[wo];
        }
        #pragma unroll
        for (int it = 0; it < 8; it++) {
            int idx = it * 256 + t;
            int row = idx >> 4, f4 = idx & 15;
            unsigned h0, l0, h1, l1;
            bf16split2(av[it].x, av[it].y, h0, l0);
            bf16split2(av[it].z, av[it].w, h1, l1);
            uint32_t off = SWZ(row * 128 + f4 * 8);
            asm volatile("st.shared.v2.b32 [%0], {%1,%2};" :: "r"(sb + L2_AH(s) + off), "r"(h0), "r"(h1) : "memory");
            asm volatile("st.shared.v2.b32 [%0], {%1,%2};" :: "r"(sb + L2_AL(s) + off), "r"(l0), "r"(l1) : "memory");
        }
        if (t < 128) {
            uint32_t off = SWZ(hr * 128 + q * 16);
            asm volatile("st.shared.v4.b32 [%0], {%1,%2,%3,%4};" :: "r"(sb + L2_BH(s) + off),
                         "r"(bh.x), "r"(bh.y), "r"(bh.z), "r"(bh.w) : "memory");
            asm volatile("st.shared.v4.b32 [%0], {%1,%2,%3,%4};" :: "r"(sb + L2_BL(s) + off),
                         "r"(bl.x), "r"(bl.y), "r"(bl.z), "r"(bl.w) : "memory");
        }
        __syncthreads();
        if (wid == 0) {
            FENCE_ASYNC();
            if (elect_one()) {
                ull adh = MK_DESC(sb + L2_AH(s)), adl = MK_DESC(sb + L2_AL(s));
                ull bdh = MK_DESC(sb + L2_BH(s)), bdl = MK_DESC(sb + L2_BL(s));
                #pragma unroll
                for (int ks = 0; ks < 4; ks++) {
                    mma_bf16_ss(tb, adh + ks * 2, bdh + ks * 2, IDESC2, !(c == 0 && ks == 0));
                    mma_bf16_ss(tb, adh + ks * 2, bdl + ks * 2, IDESC2, 1);
                    mma_bf16_ss(tb, adl + ks * 2, bdh + ks * 2, IDESC2, 1);
                }
                TC_COMMIT(sb + L1_MB + s * 8);
            }
        }
        #pragma unroll
        for (int i = 0; i < 8; i++) av[i] = avn[i];
    }
    MBAR_WAIT(sb + L1_MB + 8, 1);
    TC_FENCE_AFTER();
    if (wid < 4) {
        int row_local = wid * 32 + lane;
        uint32_t dreg[16];
        LDTM_X16(dreg, tb);
        TC_WAIT_LD();
        int gi = b * NN + i0 + row_local;
        float* P = g_p2[kc];
        size_t base4 = ((size_t)gi * CC) >> 2;
        #pragma unroll
        for (int q2 = 0; q2 < 4; q2++) {
            float4 o;
            o.x = __uint_as_float(dreg[q2 * 4 + 0]);
            o.y = __uint_as_float(dreg[q2 * 4 + 1]);
            o.z = __uint_as_float(dreg[q2 * 4 + 2]);
            o.w = __uint_as_float(dreg[q2 * 4 + 3]);
            reinterpret_cast<float4*>(P)[base4 + q2] = o;
        }
    }
    __threadfence();
    __syncthreads();
    if (t == 0) { MBAR_INVAL(sb + L1_MB); MBAR_INVAL(sb + L1_MB + 8); }
    if (wid == 0) TC_DEALLOC(tb, 32);
    if (t == 0) { *sflag = (int)atomicAdd(&g_cnt2[b * 16 + blockIdx.x], 1u); __threadfence(); }
    __syncthreads();
    if (*sflag == 0) return;
    l2_epilogue(b, i0, b2v, out);
#else
    // ---------- FFMA2 fallback: partials ----------
    float (*As)[68] = reinterpret_cast<float(*)[68]>(smem + 1024);
    float (*Bs)[16] = reinterpret_cast<float(*)[16]>(smem + 1024 + 128 * 68 * 4);
    const int cp = t & 7, rg = t >> 3;
    ull acc[4];
    #pragma unroll
    for (int r = 0; r < 4; r++) acc[r] = 0ull;
    for (int k0 = kc * KCH; k0 < kc * KCH + KCH; k0 += 64) {
        #pragma unroll
        for (int it = 0; it < 8; it++) {
            int idx = it * 256 + t;
            int row = idx >> 4, f4 = idx & 15;
            float4 v = *reinterpret_cast<const float4*>(Ab + (size_t)row * NN + k0 + f4 * 4);
            *reinterpret_cast<float4*>(&As[row][f4 * 4]) = v;
        }
        {
            int kk = t >> 2, f4 = t & 3;
            float4 v = *reinterpret_cast<const float4*>(g_M2 + ((size_t)(b * NN + k0 + kk)) * CC + f4 * 4);
            *reinterpret_cast<float4*>(&Bs[kk][f4 * 4]) = v;
        }
        __syncthreads();
        #pragma unroll 8
        for (int kk = 0; kk < 64; kk++) {
            ull bb = *reinterpret_cast<const ull*>(&Bs[kk][cp * 2]);
            #pragma unroll
            for (int r = 0; r < 4; r++) {
                float a = As[rg + 32 * r][kk];
                acc[r] = f2fma(f2pack(a, a), bb, acc[r]);
            }
        }
        __syncthreads();
    }
    float* P = g_p2[kc];
    #pragma unroll
    for (int r = 0; r < 4; r++) {
        int gi = b * NN + i0 + rg + 32 * r;
        float2 v = f2unpack(acc[r]);
        *reinterpret_cast<float2*>(&P[(size_t)gi * CC + cp * 2]) = make_float2(v.x, v.y);
    }
    __threadfence();
    __syncthreads();
    if (t == 0) { *sflag = (int)atomicAdd(&g_cnt2[b * 16 + blockIdx.x], 1u); __threadfence(); }
    __syncthreads();
    if (*sflag == 0) return;
    l2_epilogue(b, i0, b2v, out);
#endif
}

// ============================================================
extern "C" void kernel_launch(void* const* d_in, const int* in_sizes, int n_in,
                              void* d_out, int out_size) {
    const float* X  = (const float*)d_in[0];
    const float* A  = (const float*)d_in[1];
    const float* W1 = (const float*)d_in[2];
    const float* b1 = (const float*)d_in[3];
    const float* W2 = (const float*)d_in[4];
    const float* b2 = (const float*)d_in[5];
    float* out = (float*)d_out;

    cudaFuncSetAttribute(k_layer1, cudaFuncAttributeMaxDynamicSharedMemorySize, L1_SMEM);
    cudaFuncSetAttribute(k_layer2, cudaFuncAttributeMaxDynamicSharedMemorySize, L2_SMEM);

    k_pre<<<NROW / 8, 256>>>(A, X, W1);
    k_layer1<<<dim3(16, 8, KS), 256, L1_SMEM>>>(A, W2, b1);
    k_layer2<<<dim3(16, 8, KS), 256, L2_SMEM>>>(A, b2, out);
}